// round 1
// baseline (speedup 1.0000x reference)
#include <cuda_runtime.h>
#include <math.h>

#define NB 32
#define NCQ 256
#define NCC 3
#define NINTER 128
#define NHW 1024
#define NH 32
#define NHC 224
#define GN_N (NCQ*NHW)

// ---------------- scratch (static device memory, no allocs) ----------------
__device__ float g_ctx[NB*NCC*NHW];                 // resized context
__device__ float g_q[NB*NINTER*NHW];
__device__ float g_k[NB*NINTER*NHW];
__device__ float g_v[NB*NCQ*NHW];
__device__ float g_S[(size_t)NB*NHW*NHW];           // scores -> probs (134MB)
__device__ float g_X[NB*NCQ*NHW];                   // query + attended
__device__ float g_F[NB*NCQ*NHW];                   // fused (pre-norm)
__device__ float g_sums[NB*2];                      // per-batch sum, sumsq

// ---------------- 1. bilinear resize (here: exact integer src coords) ------
__global__ void resize_kernel(const float* __restrict__ ctx) {
    int idx = blockIdx.x * blockDim.x + threadIdx.x;       // b*1024 + p
    if (idx >= NB * NHW) return;
    int b = idx >> 10, p = idx & 1023;
    int y = p >> 5, x = p & 31;
    float sy = 7.f * y + 3.f;       // (y+0.5)*7 - 0.5
    float sx = 7.f * x + 3.f;
    int y0 = (int)floorf(sy), x0 = (int)floorf(sx);
    float fy = sy - y0, fx = sx - x0;
    int y1 = min(y0 + 1, NHC - 1), x1 = min(x0 + 1, NHC - 1);
    y0 = max(y0, 0); x0 = max(x0, 0);
#pragma unroll
    for (int c = 0; c < NCC; c++) {
        const float* base = ctx + ((size_t)b * NCC + c) * NHC * NHC;
        float v00 = base[y0 * NHC + x0], v01 = base[y0 * NHC + x1];
        float v10 = base[y1 * NHC + x0], v11 = base[y1 * NHC + x1];
        float v = (1.f - fy) * ((1.f - fx) * v00 + fx * v01)
                + fy * ((1.f - fx) * v10 + fx * v11);
        g_ctx[((size_t)b * NCC + c) * NHW + p] = v;
    }
}

// ---------------- 2a. k and v from 3-channel ctx (tiny convs) --------------
__global__ void kv_kernel(const float* __restrict__ Wk, const float* __restrict__ bk,
                          const float* __restrict__ Wv, const float* __restrict__ bv) {
    int idx = blockIdx.x * blockDim.x + threadIdx.x;       // b*(384)*1024 + ...
    int i  = idx & 1023;
    int cc = (idx >> 10) % (NINTER + NCQ);
    int b  = idx / ((NINTER + NCQ) * NHW);
    const float* cb = g_ctx + (size_t)b * NCC * NHW;
    float c0 = cb[i], c1 = cb[NHW + i], c2 = cb[2 * NHW + i];
    if (cc < NINTER) {
        float r = bk[cc] + Wk[cc*3]*c0 + Wk[cc*3+1]*c1 + Wk[cc*3+2]*c2;
        g_k[((size_t)b * NINTER + cc) * NHW + i] = r;
    } else {
        int c = cc - NINTER;
        float r = bv[c] + Wv[c*3]*c0 + Wv[c*3+1]*c1 + Wv[c*3+2]*c2;
        g_v[((size_t)b * NCQ + c) * NHW + i] = r;
    }
}

// ---------------- tiled GEMMs: 64x64 tile, 16x16 threads, 4x4/thread -------
// C[b][m][n] = sum_k A[m][k] * Bm[b][k][n] + bias[m]     (A unbatched, row-major)
__global__ void gemm_AB(const float* __restrict__ A, const float* __restrict__ Bm,
                        float* __restrict__ C, const float* __restrict__ bias,
                        int M, int N, int K) {
    __shared__ float As[16][68];
    __shared__ float Bs[16][68];
    int b = blockIdx.z;
    const float* Bp = Bm + (size_t)b * K * N;
    float* Cp = C + (size_t)b * M * N;
    int m0 = blockIdx.y * 64, n0 = blockIdx.x * 64;
    int tx = threadIdx.x, ty = threadIdx.y, t = ty * 16 + tx;
    float acc[4][4] = {};
    for (int kt = 0; kt < K; kt += 16) {
        __syncthreads();
        {   // A tile transposed on load
            int m = t >> 2, k4 = (t & 3) * 4;
            float4 v = *(const float4*)&A[(size_t)(m0 + m) * K + kt + k4];
            As[k4+0][m] = v.x; As[k4+1][m] = v.y; As[k4+2][m] = v.z; As[k4+3][m] = v.w;
        }
        {   // B tile direct
            int k = t >> 4, n4 = (t & 15) * 4;
            *(float4*)&Bs[k][n4] = *(const float4*)&Bp[(size_t)(kt + k) * N + n0 + n4];
        }
        __syncthreads();
#pragma unroll
        for (int kk = 0; kk < 16; kk++) {
            float4 a = *(const float4*)&As[kk][ty * 4];
            float4 bb = *(const float4*)&Bs[kk][tx * 4];
            float av[4] = {a.x, a.y, a.z, a.w};
            float bw[4] = {bb.x, bb.y, bb.z, bb.w};
#pragma unroll
            for (int i = 0; i < 4; i++)
#pragma unroll
                for (int j = 0; j < 4; j++) acc[i][j] += av[i] * bw[j];
        }
    }
#pragma unroll
    for (int i = 0; i < 4; i++) {
        int m = m0 + ty * 4 + i;
        float bi = bias ? bias[m] : 0.f;
        float4 r;
        r.x = acc[i][0] + bi; r.y = acc[i][1] + bi;
        r.z = acc[i][2] + bi; r.w = acc[i][3] + bi;
        *(float4*)&Cp[(size_t)m * N + n0 + tx * 4] = r;
    }
}

// C[b][m][n] = sum_k A[b][k][m] * Bm[b][k][n]    (both K-major, batched)
__global__ void gemm_ATB(const float* __restrict__ A, const float* __restrict__ Bm,
                         float* __restrict__ C, int M, int N, int K) {
    __shared__ float As[16][68];
    __shared__ float Bs[16][68];
    int b = blockIdx.z;
    const float* Ap = A + (size_t)b * K * M;
    const float* Bp = Bm + (size_t)b * K * N;
    float* Cp = C + (size_t)b * M * N;
    int m0 = blockIdx.y * 64, n0 = blockIdx.x * 64;
    int tx = threadIdx.x, ty = threadIdx.y, t = ty * 16 + tx;
    float acc[4][4] = {};
    for (int kt = 0; kt < K; kt += 16) {
        __syncthreads();
        {
            int k = t >> 4, m4 = (t & 15) * 4;
            *(float4*)&As[k][m4] = *(const float4*)&Ap[(size_t)(kt + k) * M + m0 + m4];
            *(float4*)&Bs[k][m4] = *(const float4*)&Bp[(size_t)(kt + k) * N + n0 + m4];
        }
        __syncthreads();
#pragma unroll
        for (int kk = 0; kk < 16; kk++) {
            float4 a = *(const float4*)&As[kk][ty * 4];
            float4 bb = *(const float4*)&Bs[kk][tx * 4];
            float av[4] = {a.x, a.y, a.z, a.w};
            float bw[4] = {bb.x, bb.y, bb.z, bb.w};
#pragma unroll
            for (int i = 0; i < 4; i++)
#pragma unroll
                for (int j = 0; j < 4; j++) acc[i][j] += av[i] * bw[j];
        }
    }
#pragma unroll
    for (int i = 0; i < 4; i++) {
        int m = m0 + ty * 4 + i;
        float4 r;
        r.x = acc[i][0]; r.y = acc[i][1]; r.z = acc[i][2]; r.w = acc[i][3];
        *(float4*)&Cp[(size_t)m * N + n0 + tx * 4] = r;
    }
}

// C[b][m][n] = sum_k A[b][m][k] * Bt[b][n][k] + addend[b][m][n]
__global__ void gemm_ABT(const float* __restrict__ A, const float* __restrict__ Bt,
                         float* __restrict__ C, const float* __restrict__ addend,
                         int M, int N, int K) {
    __shared__ float As[16][68];
    __shared__ float Bs[16][68];
    int b = blockIdx.z;
    const float* Ap = A + (size_t)b * M * K;
    const float* Bp = Bt + (size_t)b * N * K;
    float* Cp = C + (size_t)b * M * N;
    const float* Dp = addend ? addend + (size_t)b * M * N : nullptr;
    int m0 = blockIdx.y * 64, n0 = blockIdx.x * 64;
    int tx = threadIdx.x, ty = threadIdx.y, t = ty * 16 + tx;
    float acc[4][4] = {};
    for (int kt = 0; kt < K; kt += 16) {
        __syncthreads();
        {
            int m = t >> 2, k4 = (t & 3) * 4;
            float4 v = *(const float4*)&Ap[(size_t)(m0 + m) * K + kt + k4];
            As[k4+0][m] = v.x; As[k4+1][m] = v.y; As[k4+2][m] = v.z; As[k4+3][m] = v.w;
            float4 w = *(const float4*)&Bp[(size_t)(n0 + m) * K + kt + k4];
            Bs[k4+0][m] = w.x; Bs[k4+1][m] = w.y; Bs[k4+2][m] = w.z; Bs[k4+3][m] = w.w;
        }
        __syncthreads();
#pragma unroll
        for (int kk = 0; kk < 16; kk++) {
            float4 a = *(const float4*)&As[kk][ty * 4];
            float4 bb = *(const float4*)&Bs[kk][tx * 4];
            float av[4] = {a.x, a.y, a.z, a.w};
            float bw[4] = {bb.x, bb.y, bb.z, bb.w};
#pragma unroll
            for (int i = 0; i < 4; i++)
#pragma unroll
                for (int j = 0; j < 4; j++) acc[i][j] += av[i] * bw[j];
        }
    }
#pragma unroll
    for (int i = 0; i < 4; i++) {
        int m = m0 + ty * 4 + i;
        float4 r;
        r.x = acc[i][0]; r.y = acc[i][1]; r.z = acc[i][2]; r.w = acc[i][3];
        if (Dp) {
            float4 d = *(const float4*)&Dp[(size_t)m * N + n0 + tx * 4];
            r.x += d.x; r.y += d.y; r.z += d.z; r.w += d.w;
        }
        *(float4*)&Cp[(size_t)m * N + n0 + tx * 4] = r;
    }
}

// ---------------- 4. row softmax (in place on g_S) --------------------------
__global__ void softmax_kernel() {
    int row = blockIdx.x;                   // b*1024 + i
    float* p = g_S + (size_t)row * NHW;
    int t = threadIdx.x;                    // 256 threads, 4 elems each
    float4 v = ((float4*)p)[t];
    float m = fmaxf(fmaxf(v.x, v.y), fmaxf(v.z, v.w));
    __shared__ float red[8];
#pragma unroll
    for (int o = 16; o; o >>= 1) m = fmaxf(m, __shfl_xor_sync(0xffffffffu, m, o));
    if ((t & 31) == 0) red[t >> 5] = m;
    __syncthreads();
    float bmax = red[0];
#pragma unroll
    for (int i = 1; i < 8; i++) bmax = fmaxf(bmax, red[i]);
    __syncthreads();
    v.x = __expf(v.x - bmax); v.y = __expf(v.y - bmax);
    v.z = __expf(v.z - bmax); v.w = __expf(v.w - bmax);
    float s = v.x + v.y + v.z + v.w;
#pragma unroll
    for (int o = 16; o; o >>= 1) s += __shfl_xor_sync(0xffffffffu, s, o);
    if ((t & 31) == 0) red[t >> 5] = s;
    __syncthreads();
    float tot = 0.f;
#pragma unroll
    for (int i = 0; i < 8; i++) tot += red[i];
    float inv = 1.f / tot;
    v.x *= inv; v.y *= inv; v.z *= inv; v.w *= inv;
    ((float4*)p)[t] = v;
}

// ---------------- 7a. per-batch sum / sumsq of fused ------------------------
__global__ void stats_kernel() {
    int b = blockIdx.x;
    const float* p = g_F + (size_t)b * GN_N;
    float s = 0.f, s2 = 0.f;
    for (int i = threadIdx.x; i < GN_N; i += blockDim.x) {
        float v = p[i]; s += v; s2 += v * v;
    }
    __shared__ float shs[32], shq[32];
#pragma unroll
    for (int o = 16; o; o >>= 1) {
        s  += __shfl_xor_sync(0xffffffffu, s, o);
        s2 += __shfl_xor_sync(0xffffffffu, s2, o);
    }
    int w = threadIdx.x >> 5;
    if ((threadIdx.x & 31) == 0) { shs[w] = s; shq[w] = s2; }
    __syncthreads();
    if (threadIdx.x < 32) {
        s = shs[threadIdx.x]; s2 = shq[threadIdx.x];
#pragma unroll
        for (int o = 16; o; o >>= 1) {
            s  += __shfl_xor_sync(0xffffffffu, s, o);
            s2 += __shfl_xor_sync(0xffffffffu, s2, o);
        }
        if (threadIdx.x == 0) { g_sums[b * 2] = s; g_sums[b * 2 + 1] = s2; }
    }
}

// ---------------- 7b. normalize + affine -> out ------------------------------
__global__ void norm_kernel(const float* __restrict__ gamma, const float* __restrict__ beta,
                            float* __restrict__ out) {
    int idx = blockIdx.x * blockDim.x + threadIdx.x;     // over B*COUT*HW
    int b = idx >> 18;                                   // / (256*1024)
    int o = (idx >> 10) & 255;
    float s = g_sums[b * 2], s2 = g_sums[b * 2 + 1];
    const float n = (float)GN_N;
    float mu = s / n;
    float var = s2 / n - mu * mu;
    float rstd = rsqrtf(var + 1e-5f);
    out[idx] = (g_F[idx] - mu) * rstd * gamma[o] + beta[o];
}

// ---------------- launch -----------------------------------------------------
extern "C" void kernel_launch(void* const* d_in, const int* in_sizes, int n_in,
                              void* d_out, int out_size) {
    const float* query = (const float*)d_in[0];
    const float* ctx   = (const float*)d_in[1];
    const float* Wq = (const float*)d_in[2];  const float* bq = (const float*)d_in[3];
    const float* Wk = (const float*)d_in[4];  const float* bk = (const float*)d_in[5];
    const float* Wv = (const float*)d_in[6];  const float* bv = (const float*)d_in[7];
    const float* Wp = (const float*)d_in[8];  const float* bp = (const float*)d_in[9];
    const float* gamma = (const float*)d_in[10];
    const float* beta  = (const float*)d_in[11];
    float* out = (float*)d_out;

    float *p_q, *p_k, *p_v, *p_S, *p_X, *p_F;
    cudaGetSymbolAddress((void**)&p_q, g_q);
    cudaGetSymbolAddress((void**)&p_k, g_k);
    cudaGetSymbolAddress((void**)&p_v, g_v);
    cudaGetSymbolAddress((void**)&p_S, g_S);
    cudaGetSymbolAddress((void**)&p_X, g_X);
    cudaGetSymbolAddress((void**)&p_F, g_F);

    dim3 thr(16, 16);

    // 1. resize
    resize_kernel<<<(NB * NHW + 255) / 256, 256>>>(ctx);
    // 2. k, v (tiny convs) and q (GEMM)
    kv_kernel<<<(NB * (NINTER + NCQ) * NHW) / 256, 256>>>(Wk, bk, Wv, bv);
    gemm_AB<<<dim3(NHW / 64, NINTER / 64, NB), thr>>>(Wq, query, p_q, bq, NINTER, NHW, NCQ);
    // 3. scores = q^T k
    gemm_ATB<<<dim3(NHW / 64, NHW / 64, NB), thr>>>(p_q, p_k, p_S, NHW, NHW, NINTER);
    // 4. softmax rows
    softmax_kernel<<<NB * NHW, 256>>>();
    // 5. attended = v * P^T, + query residual -> X
    gemm_ABT<<<dim3(NHW / 64, NCQ / 64, NB), thr>>>(p_v, p_S, p_X, query, NCQ, NHW, NHW);
    // 6. fused = Wp * X + bp
    gemm_AB<<<dim3(NHW / 64, NCQ / 64, NB), thr>>>(Wp, p_X, p_F, bp, NCQ, NHW, NCQ);
    // 7. group norm (1 group)
    stats_kernel<<<NB, 1024>>>();
    norm_kernel<<<(NB * NCQ * NHW) / 256, 256>>>(gamma, beta, out);
}

// round 2
// speedup vs baseline: 2.0514x; 2.0514x over previous
#include <cuda_runtime.h>
#include <math.h>
#include <stdint.h>

#define NB 32
#define NCQ 256
#define NCC 3
#define NINTER 128
#define NHW 1024
#define NHC 224
#define GN_N (NCQ*NHW)

// ---------------- scratch (static device memory, no allocs) ----------------
__device__ float g_ctx[NB*NCC*NHW];                 // resized context
__device__ float g_qT[NB*NHW*NINTER];               // [b][i][c']  tf32-rounded
__device__ float g_kT[NB*NHW*NINTER];               // [b][j][c']  tf32-rounded
__device__ float g_v [NB*NCQ*NHW];                  // [b][c][j]   tf32-rounded
__device__ float g_S [(size_t)NB*NHW*NHW];          // scores -> probs (134MB)
__device__ float g_X [NB*NHW*NCQ];                  // X'[b][i][c] (query+attended, rounded)
__device__ float g_F [NB*NCQ*NHW];                  // fused F[b][o][i] (fp32)
__device__ float g_queryT[NB*NHW*NCQ];              // [b][i][c]   tf32-rounded
__device__ float g_Wq[NINTER*NCQ];                  // rounded
__device__ float g_Wp[NCQ*NCQ];                     // rounded
__device__ float g_sums[NB*2];

__device__ __forceinline__ float rna(float x) {
    float r;
    asm("cvt.rna.tf32.f32 %0, %1;" : "=f"(r) : "f"(x));
    return r;
}
__device__ __forceinline__ uint32_t fbits(float x) { return __float_as_uint(x); }

// ---------------- 1. bilinear resize -----------------------------------------
__global__ void resize_kernel(const float* __restrict__ ctx) {
    int idx = blockIdx.x * blockDim.x + threadIdx.x;       // b*1024 + p
    if (idx >= NB * NHW) return;
    int b = idx >> 10, p = idx & 1023;
    int y = p >> 5, x = p & 31;
    float sy = 7.f * y + 3.f;
    float sx = 7.f * x + 3.f;
    int y0 = (int)floorf(sy), x0 = (int)floorf(sx);
    float fy = sy - y0, fx = sx - x0;
    int y1 = min(y0 + 1, NHC - 1), x1 = min(x0 + 1, NHC - 1);
    y0 = max(y0, 0); x0 = max(x0, 0);
#pragma unroll
    for (int c = 0; c < NCC; c++) {
        const float* base = ctx + ((size_t)b * NCC + c) * NHC * NHC;
        float v00 = base[y0 * NHC + x0], v01 = base[y0 * NHC + x1];
        float v10 = base[y1 * NHC + x0], v11 = base[y1 * NHC + x1];
        float v = (1.f - fy) * ((1.f - fx) * v00 + fx * v01)
                + fy * ((1.f - fx) * v10 + fx * v11);
        g_ctx[((size_t)b * NCC + c) * NHW + p] = v;
    }
}

// ---------------- 2a. kT[b][j][c'] (tiny conv, rounded) -----------------------
__global__ void kproj_kernel(const float* __restrict__ Wk, const float* __restrict__ bk) {
    int idx = blockIdx.x * blockDim.x + threadIdx.x;  // NB*NHW*NINTER
    int c = idx & 127;
    int j = (idx >> 7) & 1023;
    int b = idx >> 17;
    const float* cb = g_ctx + (size_t)b * NCC * NHW;
    float c0 = cb[j], c1 = cb[NHW + j], c2 = cb[2 * NHW + j];
    g_kT[idx] = rna(bk[c] + Wk[c*3]*c0 + Wk[c*3+1]*c1 + Wk[c*3+2]*c2);
}

// ---------------- 2b. v[b][c][j] (tiny conv, rounded) -------------------------
__global__ void vproj_kernel(const float* __restrict__ Wv, const float* __restrict__ bv) {
    int idx = blockIdx.x * blockDim.x + threadIdx.x;  // NB*NCQ*NHW
    int i = idx & 1023;
    int c = (idx >> 10) & 255;
    int b = idx >> 18;
    const float* cb = g_ctx + (size_t)b * NCC * NHW;
    float c0 = cb[i], c1 = cb[NHW + i], c2 = cb[2 * NHW + i];
    g_v[idx] = rna(bv[c] + Wv[c*3]*c0 + Wv[c*3+1]*c1 + Wv[c*3+2]*c2);
}

// ---------------- queryT transpose + round ------------------------------------
__global__ void transpose_round(const float* __restrict__ in) {
    __shared__ float t[32][33];
    int b = blockIdx.z;
    int i0 = blockIdx.x * 32, c0 = blockIdx.y * 32;
    const float* ip = in + (size_t)b * NCQ * NHW;
    float* op = g_queryT + (size_t)b * NHW * NCQ;
    t[threadIdx.y][threadIdx.x] = ip[(size_t)(c0 + threadIdx.y) * NHW + i0 + threadIdx.x];
    __syncthreads();
    op[(size_t)(i0 + threadIdx.y) * NCQ + c0 + threadIdx.x] = rna(t[threadIdx.x][threadIdx.y]);
}

// ---------------- weight rounding ----------------------------------------------
__global__ void prep_weights(const float* __restrict__ Wq, const float* __restrict__ Wp) {
    int i = blockIdx.x * blockDim.x + threadIdx.x;
    if (i < NINTER * NCQ) g_Wq[i] = rna(Wq[i]);
    if (i < NCQ * NCQ)    g_Wp[i] = rna(Wp[i]);
}

// ---------------- tf32 tensor-core ABT GEMM ------------------------------------
// C[b][m][n] = sum_k A[b][m][k] * B[b][n][k]  (+bias_m[m]) (+bias_n[n]) (+addend[b][m][n])
// BM=BN=128, BK=16, 256 threads (8 warps as 2x4, warp tile 64x32), double buffered.
#define SMP 20   // smem row pitch (16 cols + 4 pad)
__global__ __launch_bounds__(256, 2)
void gemm_tc(const float* __restrict__ A, const float* __restrict__ B, float* __restrict__ C,
             size_t sA, size_t sB, size_t sC,
             const float* __restrict__ bias_m, const float* __restrict__ bias_n,
             const float* __restrict__ addend,
             int M, int N, int K, int roundOut) {
    __shared__ float As[2][128 * SMP];
    __shared__ float Bs[2][128 * SMP];
    int b = blockIdx.z;
    A += (size_t)b * sA; B += (size_t)b * sB; C += (size_t)b * sC;
    if (addend) addend += (size_t)b * sC;
    int m0 = blockIdx.y * 128, n0 = blockIdx.x * 128;
    int tid = threadIdx.x, lane = tid & 31, wid = tid >> 5;
    int wm = wid >> 2, wn = wid & 3;              // warp grid 2(m) x 4(n)
    int gid = lane >> 2, tig = lane & 3;          // mma groupID / tid-in-group

    float acc[4][4][4];
#pragma unroll
    for (int i = 0; i < 4; i++)
#pragma unroll
        for (int j = 0; j < 4; j++)
#pragma unroll
            for (int r = 0; r < 4; r++) acc[i][j][r] = 0.f;

    // gmem tile load: 2 float4 per thread per operand
    int lrow0 = tid >> 2,        lc4_0 = (tid & 3) * 4;          // loads 0..255
    int lrow1 = (tid + 256) >> 2, lc4_1 = lc4_0;                 // loads 256..511
    int nk = K / 16;
    float4 ra0, ra1, rb0, rb1;

    // prologue: tile 0
    ra0 = *(const float4*)&A[(size_t)(m0 + lrow0) * K + lc4_0];
    ra1 = *(const float4*)&A[(size_t)(m0 + lrow1) * K + lc4_1];
    rb0 = *(const float4*)&B[(size_t)(n0 + lrow0) * K + lc4_0];
    rb1 = *(const float4*)&B[(size_t)(n0 + lrow1) * K + lc4_1];
    {
        float* a = &As[0][lrow0 * SMP + lc4_0];
        a[0] = ra0.x; a[1] = ra0.y; a[2] = ra0.z; a[3] = ra0.w;
        a = &As[0][lrow1 * SMP + lc4_1];
        a[0] = ra1.x; a[1] = ra1.y; a[2] = ra1.z; a[3] = ra1.w;
        float* p = &Bs[0][lrow0 * SMP + lc4_0];
        p[0] = rb0.x; p[1] = rb0.y; p[2] = rb0.z; p[3] = rb0.w;
        p = &Bs[0][lrow1 * SMP + lc4_1];
        p[0] = rb1.x; p[1] = rb1.y; p[2] = rb1.z; p[3] = rb1.w;
    }
    __syncthreads();

    for (int kt = 0; kt < nk; kt++) {
        int cur = kt & 1;
        if (kt + 1 < nk) {
            int kb = (kt + 1) * 16;
            ra0 = *(const float4*)&A[(size_t)(m0 + lrow0) * K + kb + lc4_0];
            ra1 = *(const float4*)&A[(size_t)(m0 + lrow1) * K + kb + lc4_1];
            rb0 = *(const float4*)&B[(size_t)(n0 + lrow0) * K + kb + lc4_0];
            rb1 = *(const float4*)&B[(size_t)(n0 + lrow1) * K + kb + lc4_1];
        }
#pragma unroll
        for (int ks = 0; ks < 2; ks++) {
            int k0 = ks * 8;
            uint32_t afr[4][4], bfr[4][2];
#pragma unroll
            for (int mt = 0; mt < 4; mt++) {
                const float* ap = &As[cur][(wm * 64 + mt * 16 + gid) * SMP + k0 + tig];
                afr[mt][0] = fbits(ap[0]);
                afr[mt][1] = fbits(ap[8 * SMP]);
                afr[mt][2] = fbits(ap[4]);
                afr[mt][3] = fbits(ap[8 * SMP + 4]);
            }
#pragma unroll
            for (int nt = 0; nt < 4; nt++) {
                const float* bp = &Bs[cur][(wn * 32 + nt * 8 + gid) * SMP + k0 + tig];
                bfr[nt][0] = fbits(bp[0]);
                bfr[nt][1] = fbits(bp[4]);
            }
#pragma unroll
            for (int mt = 0; mt < 4; mt++)
#pragma unroll
                for (int nt = 0; nt < 4; nt++) {
                    asm volatile(
                        "mma.sync.aligned.m16n8k8.row.col.f32.tf32.tf32.f32 "
                        "{%0,%1,%2,%3}, {%4,%5,%6,%7}, {%8,%9}, {%0,%1,%2,%3};"
                        : "+f"(acc[mt][nt][0]), "+f"(acc[mt][nt][1]),
                          "+f"(acc[mt][nt][2]), "+f"(acc[mt][nt][3])
                        : "r"(afr[mt][0]), "r"(afr[mt][1]), "r"(afr[mt][2]), "r"(afr[mt][3]),
                          "r"(bfr[nt][0]), "r"(bfr[nt][1]));
                }
        }
        if (kt + 1 < nk) {
            int nxt = cur ^ 1;
            float* a = &As[nxt][lrow0 * SMP + lc4_0];
            a[0] = ra0.x; a[1] = ra0.y; a[2] = ra0.z; a[3] = ra0.w;
            a = &As[nxt][lrow1 * SMP + lc4_1];
            a[0] = ra1.x; a[1] = ra1.y; a[2] = ra1.z; a[3] = ra1.w;
            float* p = &Bs[nxt][lrow0 * SMP + lc4_0];
            p[0] = rb0.x; p[1] = rb0.y; p[2] = rb0.z; p[3] = rb0.w;
            p = &Bs[nxt][lrow1 * SMP + lc4_1];
            p[0] = rb1.x; p[1] = rb1.y; p[2] = rb1.z; p[3] = rb1.w;
        }
        __syncthreads();
    }

    // epilogue
#pragma unroll
    for (int mt = 0; mt < 4; mt++) {
#pragma unroll
        for (int nt = 0; nt < 4; nt++) {
            int row0 = m0 + wm * 64 + mt * 16 + gid;
            int col  = n0 + wn * 32 + nt * 8 + tig * 2;
#pragma unroll
            for (int h = 0; h < 2; h++) {
                int row = row0 + h * 8;
                float x = acc[mt][nt][h * 2], y = acc[mt][nt][h * 2 + 1];
                if (bias_m) { float bm = bias_m[row]; x += bm; y += bm; }
                if (bias_n) { x += bias_n[col]; y += bias_n[col + 1]; }
                if (addend) {
                    float2 d = *(const float2*)&addend[(size_t)row * N + col];
                    x += d.x; y += d.y;
                }
                if (roundOut) { x = rna(x); y = rna(y); }
                float2 r; r.x = x; r.y = y;
                *(float2*)&C[(size_t)row * N + col] = r;
            }
        }
    }
}

// ---------------- 4. row softmax (in place on g_S, rounded output) -------------
__global__ void softmax_kernel() {
    int row = blockIdx.x;                   // b*1024 + i
    float* p = g_S + (size_t)row * NHW;
    int t = threadIdx.x;                    // 256 threads, 4 elems each
    float4 v = ((float4*)p)[t];
    float m = fmaxf(fmaxf(v.x, v.y), fmaxf(v.z, v.w));
    __shared__ float red[8];
#pragma unroll
    for (int o = 16; o; o >>= 1) m = fmaxf(m, __shfl_xor_sync(0xffffffffu, m, o));
    if ((t & 31) == 0) red[t >> 5] = m;
    __syncthreads();
    float bmax = red[0];
#pragma unroll
    for (int i = 1; i < 8; i++) bmax = fmaxf(bmax, red[i]);
    __syncthreads();
    v.x = __expf(v.x - bmax); v.y = __expf(v.y - bmax);
    v.z = __expf(v.z - bmax); v.w = __expf(v.w - bmax);
    float s = v.x + v.y + v.z + v.w;
#pragma unroll
    for (int o = 16; o; o >>= 1) s += __shfl_xor_sync(0xffffffffu, s, o);
    if ((t & 31) == 0) red[t >> 5] = s;
    __syncthreads();
    float tot = 0.f;
#pragma unroll
    for (int i = 0; i < 8; i++) tot += red[i];
    float inv = 1.f / tot;
    v.x = rna(v.x * inv); v.y = rna(v.y * inv);
    v.z = rna(v.z * inv); v.w = rna(v.w * inv);
    ((float4*)p)[t] = v;
}

// ---------------- 7a. per-batch sum / sumsq of fused ----------------------------
__global__ void stats_kernel() {
    int b = blockIdx.x;
    const float* p = g_F + (size_t)b * GN_N;
    float s = 0.f, s2 = 0.f;
    for (int i = threadIdx.x; i < GN_N; i += blockDim.x) {
        float v = p[i]; s += v; s2 += v * v;
    }
    __shared__ float shs[32], shq[32];
#pragma unroll
    for (int o = 16; o; o >>= 1) {
        s  += __shfl_xor_sync(0xffffffffu, s, o);
        s2 += __shfl_xor_sync(0xffffffffu, s2, o);
    }
    int w = threadIdx.x >> 5;
    if ((threadIdx.x & 31) == 0) { shs[w] = s; shq[w] = s2; }
    __syncthreads();
    if (threadIdx.x < 32) {
        s = shs[threadIdx.x]; s2 = shq[threadIdx.x];
#pragma unroll
        for (int o = 16; o; o >>= 1) {
            s  += __shfl_xor_sync(0xffffffffu, s, o);
            s2 += __shfl_xor_sync(0xffffffffu, s2, o);
        }
        if (threadIdx.x == 0) { g_sums[b * 2] = s; g_sums[b * 2 + 1] = s2; }
    }
}

// ---------------- 7b. normalize + affine -> out ----------------------------------
__global__ void norm_kernel(const float* __restrict__ gamma, const float* __restrict__ beta,
                            float* __restrict__ out) {
    int idx = blockIdx.x * blockDim.x + threadIdx.x;     // over B*COUT*HW
    int b = idx >> 18;
    int o = (idx >> 10) & 255;
    float s = g_sums[b * 2], s2 = g_sums[b * 2 + 1];
    const float n = (float)GN_N;
    float mu = s / n;
    float var = s2 / n - mu * mu;
    float rstd = rsqrtf(var + 1e-5f);
    out[idx] = (g_F[idx] - mu) * rstd * gamma[o] + beta[o];
}

// ---------------- launch ----------------------------------------------------------
extern "C" void kernel_launch(void* const* d_in, const int* in_sizes, int n_in,
                              void* d_out, int out_size) {
    const float* query = (const float*)d_in[0];
    const float* ctx   = (const float*)d_in[1];
    const float* Wq = (const float*)d_in[2];  const float* bq = (const float*)d_in[3];
    const float* Wk = (const float*)d_in[4];  const float* bk = (const float*)d_in[5];
    const float* Wv = (const float*)d_in[6];  const float* bv = (const float*)d_in[7];
    const float* Wp = (const float*)d_in[8];  const float* bp = (const float*)d_in[9];
    const float* gamma = (const float*)d_in[10];
    const float* beta  = (const float*)d_in[11];
    float* out = (float*)d_out;

    float *p_qT, *p_kT, *p_v, *p_S, *p_X, *p_F, *p_queryT, *p_Wq, *p_Wp;
    cudaGetSymbolAddress((void**)&p_qT, g_qT);
    cudaGetSymbolAddress((void**)&p_kT, g_kT);
    cudaGetSymbolAddress((void**)&p_v, g_v);
    cudaGetSymbolAddress((void**)&p_S, g_S);
    cudaGetSymbolAddress((void**)&p_X, g_X);
    cudaGetSymbolAddress((void**)&p_F, g_F);
    cudaGetSymbolAddress((void**)&p_queryT, g_queryT);
    cudaGetSymbolAddress((void**)&p_Wq, g_Wq);
    cudaGetSymbolAddress((void**)&p_Wp, g_Wp);

    // preprocessing
    resize_kernel<<<(NB * NHW + 255) / 256, 256>>>(ctx);
    prep_weights<<<256, 256>>>(Wq, Wp);
    transpose_round<<<dim3(NHW / 32, NCQ / 32, NB), dim3(32, 32)>>>(query);
    kproj_kernel<<<(NB * NHW * NINTER) / 256, 256>>>(Wk, bk);
    vproj_kernel<<<(NB * NCQ * NHW) / 256, 256>>>(Wv, bv);

    // 1. qT[i][c'] = queryT[i][c] x Wq[c'][c] + bq   (M=1024, N=128, K=256)
    gemm_tc<<<dim3(NINTER / 128, NHW / 128, NB), 256>>>(
        p_queryT, p_Wq, p_qT,
        (size_t)NHW * NCQ, 0, (size_t)NHW * NINTER,
        nullptr, bq, nullptr, NHW, NINTER, NCQ, 1);

    // 2. S[i][j] = qT[i][:] . kT[j][:]   (M=N=1024, K=128)
    gemm_tc<<<dim3(NHW / 128, NHW / 128, NB), 256>>>(
        p_qT, p_kT, p_S,
        (size_t)NHW * NINTER, (size_t)NHW * NINTER, (size_t)NHW * NHW,
        nullptr, nullptr, nullptr, NHW, NHW, NINTER, 0);

    // 3. softmax rows (rounds output)
    softmax_kernel<<<NB * NHW, 256>>>();

    // 4. X'[i][c] = P[i][:] . v[c][:] + queryT[i][c]   (M=1024, N=256, K=1024)
    gemm_tc<<<dim3(NCQ / 128, NHW / 128, NB), 256>>>(
        p_S, p_v, p_X,
        (size_t)NHW * NHW, (size_t)NCQ * NHW, (size_t)NHW * NCQ,
        nullptr, nullptr, p_queryT, NHW, NCQ, NHW, 1);

    // 5. F[o][i] = Wp[o][:] . X'[i][:] + bp[o]   (M=256, N=1024, K=256)
    gemm_tc<<<dim3(NHW / 128, NCQ / 128, NB), 256>>>(
        p_Wp, p_X, p_F,
        0, (size_t)NHW * NCQ, (size_t)NCQ * NHW,
        bp, nullptr, nullptr, NCQ, NHW, NCQ, 0);

    // 6. group norm (1 group)
    stats_kernel<<<NB, 1024>>>();
    norm_kernel<<<(NB * NCQ * NHW) / 256, 256>>>(gamma, beta, out);
}

// round 3
// speedup vs baseline: 2.2293x; 1.0867x over previous
#include <cuda_runtime.h>
#include <math.h>
#include <stdint.h>

#define NB 32
#define NCQ 256
#define NCC 3
#define NINTER 128
#define NHW 1024
#define NHC 224
#define GN_N (NCQ*NHW)

// ---------------- scratch (static device memory, no allocs) ----------------
__device__ float g_ctx[NB*NCC*NHW];                 // resized context
__device__ float g_qT[NB*NHW*NINTER];               // [b][i][c']  tf32-rounded
__device__ float g_kT[NB*NHW*NINTER];               // [b][j][c']  tf32-rounded
__device__ float g_v [NB*NCQ*NHW];                  // [b][c][j]   tf32-rounded
__device__ float g_X [NB*NHW*NCQ];                  // X'[b][i][c] (query+attended, rounded)
__device__ float g_F [NB*NCQ*NHW];                  // fused F[b][o][i] (fp32)
__device__ float g_queryT[NB*NHW*NCQ];              // [b][i][c]   tf32-rounded
__device__ float g_Wq[NINTER*NCQ];                  // rounded
__device__ float g_Wp[NCQ*NCQ];                     // rounded
__device__ float g_sums[NB*2];

__device__ __forceinline__ float rna(float x) {
    float r;
    asm("cvt.rna.tf32.f32 %0, %1;" : "=f"(r) : "f"(x));
    return r;
}
__device__ __forceinline__ uint32_t fb(float x) { return __float_as_uint(x); }

__device__ __forceinline__ void mma_tf32(float* d, uint32_t a0, uint32_t a1, uint32_t a2,
                                         uint32_t a3, uint32_t b0, uint32_t b1) {
    asm volatile(
        "mma.sync.aligned.m16n8k8.row.col.f32.tf32.tf32.f32 "
        "{%0,%1,%2,%3}, {%4,%5,%6,%7}, {%8,%9}, {%0,%1,%2,%3};"
        : "+f"(d[0]), "+f"(d[1]), "+f"(d[2]), "+f"(d[3])
        : "r"(a0), "r"(a1), "r"(a2), "r"(a3), "r"(b0), "r"(b1));
}

__device__ __forceinline__ void cpa16(float* dst, const float* src) {
    uint32_t d = (uint32_t)__cvta_generic_to_shared(dst);
    asm volatile("cp.async.cg.shared.global [%0], [%1], 16;" :: "r"(d), "l"(src));
}
#define CP_COMMIT asm volatile("cp.async.commit_group;")
#define CP_WAIT1  asm volatile("cp.async.wait_group 1;")
#define CP_WAIT0  asm volatile("cp.async.wait_group 0;")

// ---------------- 1. bilinear resize -----------------------------------------
__global__ void resize_kernel(const float* __restrict__ ctx) {
    int idx = blockIdx.x * blockDim.x + threadIdx.x;
    if (idx >= NB * NHW) return;
    int b = idx >> 10, p = idx & 1023;
    int y = p >> 5, x = p & 31;
    float sy = 7.f * y + 3.f;
    float sx = 7.f * x + 3.f;
    int y0 = (int)floorf(sy), x0 = (int)floorf(sx);
    float fy = sy - y0, fx = sx - x0;
    int y1 = min(y0 + 1, NHC - 1), x1 = min(x0 + 1, NHC - 1);
    y0 = max(y0, 0); x0 = max(x0, 0);
#pragma unroll
    for (int c = 0; c < NCC; c++) {
        const float* base = ctx + ((size_t)b * NCC + c) * NHC * NHC;
        float v00 = base[y0 * NHC + x0], v01 = base[y0 * NHC + x1];
        float v10 = base[y1 * NHC + x0], v11 = base[y1 * NHC + x1];
        float v = (1.f - fy) * ((1.f - fx) * v00 + fx * v01)
                + fy * ((1.f - fx) * v10 + fx * v11);
        g_ctx[((size_t)b * NCC + c) * NHW + p] = v;
    }
}

// ---------------- 2a. kT[b][j][c'] (tiny conv, rounded) -----------------------
__global__ void kproj_kernel(const float* __restrict__ Wk, const float* __restrict__ bk) {
    int idx = blockIdx.x * blockDim.x + threadIdx.x;
    int c = idx & 127;
    int j = (idx >> 7) & 1023;
    int b = idx >> 17;
    const float* cb = g_ctx + (size_t)b * NCC * NHW;
    float c0 = cb[j], c1 = cb[NHW + j], c2 = cb[2 * NHW + j];
    g_kT[idx] = rna(bk[c] + Wk[c*3]*c0 + Wk[c*3+1]*c1 + Wk[c*3+2]*c2);
}

// ---------------- 2b. v[b][c][j] (tiny conv, rounded) -------------------------
__global__ void vproj_kernel(const float* __restrict__ Wv, const float* __restrict__ bv) {
    int idx = blockIdx.x * blockDim.x + threadIdx.x;
    int i = idx & 1023;
    int c = (idx >> 10) & 255;
    int b = idx >> 18;
    const float* cb = g_ctx + (size_t)b * NCC * NHW;
    float c0 = cb[i], c1 = cb[NHW + i], c2 = cb[2 * NHW + i];
    g_v[idx] = rna(bv[c] + Wv[c*3]*c0 + Wv[c*3+1]*c1 + Wv[c*3+2]*c2);
}

// ---------------- queryT transpose + round ------------------------------------
__global__ void transpose_round(const float* __restrict__ in) {
    __shared__ float t[32][33];
    int b = blockIdx.z;
    int i0 = blockIdx.x * 32, c0 = blockIdx.y * 32;
    const float* ip = in + (size_t)b * NCQ * NHW;
    float* op = g_queryT + (size_t)b * NHW * NCQ;
    t[threadIdx.y][threadIdx.x] = ip[(size_t)(c0 + threadIdx.y) * NHW + i0 + threadIdx.x];
    __syncthreads();
    op[(size_t)(i0 + threadIdx.y) * NCQ + c0 + threadIdx.x] = rna(t[threadIdx.x][threadIdx.y]);
}

// ---------------- weight rounding ----------------------------------------------
__global__ void prep_weights(const float* __restrict__ Wq, const float* __restrict__ Wp) {
    int i = blockIdx.x * blockDim.x + threadIdx.x;
    if (i < NINTER * NCQ) g_Wq[i] = rna(Wq[i]);
    if (i < NCQ * NCQ)    g_Wp[i] = rna(Wp[i]);
}

// ---------------- tf32 tensor-core ABT GEMM (for q-proj and fused conv) ---------
#define SMP 20
__global__ __launch_bounds__(256, 2)
void gemm_tc(const float* __restrict__ A, const float* __restrict__ B, float* __restrict__ C,
             size_t sA, size_t sB, size_t sC,
             const float* __restrict__ bias_m, const float* __restrict__ bias_n,
             int M, int N, int K, int roundOut) {
    __shared__ float As[2][128 * SMP];
    __shared__ float Bs[2][128 * SMP];
    int b = blockIdx.z;
    A += (size_t)b * sA; B += (size_t)b * sB; C += (size_t)b * sC;
    int m0 = blockIdx.y * 128, n0 = blockIdx.x * 128;
    int tid = threadIdx.x, lane = tid & 31, wid = tid >> 5;
    int wm = wid >> 2, wn = wid & 3;
    int gid = lane >> 2, tig = lane & 3;

    float acc[4][4][4];
#pragma unroll
    for (int i = 0; i < 4; i++)
#pragma unroll
        for (int j = 0; j < 4; j++)
#pragma unroll
            for (int r = 0; r < 4; r++) acc[i][j][r] = 0.f;

    int lrow0 = tid >> 2,         lc4_0 = (tid & 3) * 4;
    int lrow1 = (tid + 256) >> 2, lc4_1 = lc4_0;
    int nk = K / 16;
    float4 ra0, ra1, rb0, rb1;

    ra0 = *(const float4*)&A[(size_t)(m0 + lrow0) * K + lc4_0];
    ra1 = *(const float4*)&A[(size_t)(m0 + lrow1) * K + lc4_1];
    rb0 = *(const float4*)&B[(size_t)(n0 + lrow0) * K + lc4_0];
    rb1 = *(const float4*)&B[(size_t)(n0 + lrow1) * K + lc4_1];
    {
        float* a = &As[0][lrow0 * SMP + lc4_0];
        a[0] = ra0.x; a[1] = ra0.y; a[2] = ra0.z; a[3] = ra0.w;
        a = &As[0][lrow1 * SMP + lc4_1];
        a[0] = ra1.x; a[1] = ra1.y; a[2] = ra1.z; a[3] = ra1.w;
        float* p = &Bs[0][lrow0 * SMP + lc4_0];
        p[0] = rb0.x; p[1] = rb0.y; p[2] = rb0.z; p[3] = rb0.w;
        p = &Bs[0][lrow1 * SMP + lc4_1];
        p[0] = rb1.x; p[1] = rb1.y; p[2] = rb1.z; p[3] = rb1.w;
    }
    __syncthreads();

    for (int kt = 0; kt < nk; kt++) {
        int cur = kt & 1;
        if (kt + 1 < nk) {
            int kb = (kt + 1) * 16;
            ra0 = *(const float4*)&A[(size_t)(m0 + lrow0) * K + kb + lc4_0];
            ra1 = *(const float4*)&A[(size_t)(m0 + lrow1) * K + kb + lc4_1];
            rb0 = *(const float4*)&B[(size_t)(n0 + lrow0) * K + kb + lc4_0];
            rb1 = *(const float4*)&B[(size_t)(n0 + lrow1) * K + kb + lc4_1];
        }
#pragma unroll
        for (int ks = 0; ks < 2; ks++) {
            int k0 = ks * 8;
            uint32_t afr[4][4], bfr[4][2];
#pragma unroll
            for (int mt = 0; mt < 4; mt++) {
                const float* ap = &As[cur][(wm * 64 + mt * 16 + gid) * SMP + k0 + tig];
                afr[mt][0] = fb(ap[0]);
                afr[mt][1] = fb(ap[8 * SMP]);
                afr[mt][2] = fb(ap[4]);
                afr[mt][3] = fb(ap[8 * SMP + 4]);
            }
#pragma unroll
            for (int nt = 0; nt < 4; nt++) {
                const float* bp = &Bs[cur][(wn * 32 + nt * 8 + gid) * SMP + k0 + tig];
                bfr[nt][0] = fb(bp[0]);
                bfr[nt][1] = fb(bp[4]);
            }
#pragma unroll
            for (int mt = 0; mt < 4; mt++)
#pragma unroll
                for (int nt = 0; nt < 4; nt++)
                    mma_tf32(acc[mt][nt], afr[mt][0], afr[mt][1], afr[mt][2], afr[mt][3],
                             bfr[nt][0], bfr[nt][1]);
        }
        if (kt + 1 < nk) {
            int nxt = cur ^ 1;
            float* a = &As[nxt][lrow0 * SMP + lc4_0];
            a[0] = ra0.x; a[1] = ra0.y; a[2] = ra0.z; a[3] = ra0.w;
            a = &As[nxt][lrow1 * SMP + lc4_1];
            a[0] = ra1.x; a[1] = ra1.y; a[2] = ra1.z; a[3] = ra1.w;
            float* p = &Bs[nxt][lrow0 * SMP + lc4_0];
            p[0] = rb0.x; p[1] = rb0.y; p[2] = rb0.z; p[3] = rb0.w;
            p = &Bs[nxt][lrow1 * SMP + lc4_1];
            p[0] = rb1.x; p[1] = rb1.y; p[2] = rb1.z; p[3] = rb1.w;
        }
        __syncthreads();
    }

#pragma unroll
    for (int mt = 0; mt < 4; mt++) {
#pragma unroll
        for (int nt = 0; nt < 4; nt++) {
            int row0 = m0 + wm * 64 + mt * 16 + gid;
            int col  = n0 + wn * 32 + nt * 8 + tig * 2;
#pragma unroll
            for (int h = 0; h < 2; h++) {
                int row = row0 + h * 8;
                float x = acc[mt][nt][h * 2], y = acc[mt][nt][h * 2 + 1];
                if (bias_m) { float bm = bias_m[row]; x += bm; y += bm; }
                if (bias_n) { x += bias_n[col]; y += bias_n[col + 1]; }
                if (roundOut) { x = rna(x); y = rna(y); }
                float2 r; r.x = x; r.y = y;
                *(float2*)&C[(size_t)row * N + col] = r;
            }
        }
    }
}

// ---------------- flash attention: S=q.kT -> online softmax -> O=P.v ------------
// block: (b, i-tile of 64). 256 threads (8 warps). j-tiles of 64, 16 iterations.
#define IT 64
#define JT 64
#define QP 132
#define KP 132
#define VP 68
#define PP 68
#define SMEM_FLOATS (IT*QP + 2*JT*KP + NCQ*VP + IT*PP + IT*4 + IT*4 + IT + IT)

__global__ __launch_bounds__(256, 1)
void flash_kernel(const float* __restrict__ qT, const float* __restrict__ kT,
                  const float* __restrict__ v, const float* __restrict__ queryT,
                  float* __restrict__ X) {
    extern __shared__ float sm[];
    float* Qs   = sm;                    // IT x QP
    float* Ks   = Qs + IT * QP;          // 2 x JT x KP
    float* Vs   = Ks + 2 * JT * KP;      // NCQ x VP
    float* Ps   = Vs + NCQ * VP;         // IT x PP
    float* redm = Ps + IT * PP;          // IT x 4
    float* reds = redm + IT * 4;         // IT x 4
    float* m_s  = reds + IT * 4;         // IT
    float* l_s  = m_s + IT;              // IT

    int b = blockIdx.y, i0 = blockIdx.x * IT;
    const float* qTb = qT + ((size_t)b * NHW + i0) * NINTER;
    const float* kTb = kT + (size_t)b * NHW * NINTER;
    const float* vb  = v  + (size_t)b * NCQ * NHW;

    int tid = threadIdx.x, lane = tid & 31, w = tid >> 5;
    int gid = lane >> 2, tig = lane & 3;
    // gemm1 mapping: 4(m) x 2(n), warp tile 16x32
    int wm1 = w >> 1, wn1 = w & 1;
    // gemm2 mapping: 2(m) x 4(n), warp tile 32x64
    int wm2 = w >> 2, wn2 = w & 3;

    // load Q tile (64 x 128)
#pragma unroll
    for (int it = 0; it < 8; it++) {
        int id = tid + it * 256;
        int r = id >> 5, c4 = (id & 31) * 4;
        *(float4*)&Qs[r * QP + c4] = *(const float4*)&qTb[(size_t)r * NINTER + c4];
    }
    if (tid < IT) { m_s[tid] = -1e30f; l_s[tid] = 0.f; }

    // prologue: prefetch K0, V0
#pragma unroll
    for (int it = 0; it < 8; it++) {
        int id = tid + it * 256;
        int r = id >> 5, c = (id & 31) * 4;
        cpa16(&Ks[r * KP + c], &kTb[(size_t)r * NINTER + c]);
    }
    CP_COMMIT;
#pragma unroll
    for (int it = 0; it < 16; it++) {
        int id = tid + it * 256;
        int r = id >> 4, c = (id & 15) * 4;
        cpa16(&Vs[r * VP + c], &vb[(size_t)r * NHW + c]);
    }
    CP_COMMIT;

    float oa[2][8][4];
#pragma unroll
    for (int mt = 0; mt < 2; mt++)
#pragma unroll
        for (int nt = 0; nt < 8; nt++)
#pragma unroll
            for (int r = 0; r < 4; r++) oa[mt][nt][r] = 0.f;

    for (int t = 0; t < 16; t++) {
        int buf = t & 1;
        __syncthreads();   // gemm2(t-1) complete (Vs, Ps free); Qs ready at t=0
        if (t > 0) {       // prefetch V(t)
            int j0 = t * JT;
#pragma unroll
            for (int it = 0; it < 16; it++) {
                int id = tid + it * 256;
                int r = id >> 4, c = (id & 15) * 4;
                cpa16(&Vs[r * VP + c], &vb[(size_t)r * NHW + j0 + c]);
            }
            CP_COMMIT;
        }
        CP_WAIT1;          // K(t) complete (V(t) may be in flight)
        __syncthreads();

        // ---- gemm1: S(16x32 per warp) = Q x K^T ----
        float s[4][4];
#pragma unroll
        for (int nt = 0; nt < 4; nt++)
#pragma unroll
            for (int r = 0; r < 4; r++) s[nt][r] = 0.f;
        {
            const float* qp = &Qs[(wm1 * 16 + gid) * QP + tig];
            const float* kp = &Ks[buf * JT * KP + (wn1 * 32 + gid) * KP + tig];
#pragma unroll
            for (int k0 = 0; k0 < NINTER; k0 += 8) {
                uint32_t a0 = fb(qp[k0]), a1 = fb(qp[8 * QP + k0]);
                uint32_t a2 = fb(qp[k0 + 4]), a3 = fb(qp[8 * QP + k0 + 4]);
#pragma unroll
                for (int nt = 0; nt < 4; nt++) {
                    uint32_t b0 = fb(kp[nt * 8 * KP + k0]);
                    uint32_t b1 = fb(kp[nt * 8 * KP + k0 + 4]);
                    mma_tf32(s[nt], a0, a1, a2, a3, b0, b1);
                }
            }
        }
        // prefetch K(t+1)
        if (t < 15) {
            int j0 = (t + 1) * JT;
            float* kd = &Ks[(buf ^ 1) * JT * KP];
#pragma unroll
            for (int it = 0; it < 8; it++) {
                int id = tid + it * 256;
                int r = id >> 5, c = (id & 31) * 4;
                cpa16(&kd[r * KP + c], &kTb[(size_t)(j0 + r) * NINTER + c]);
            }
            CP_COMMIT;
        }

        // ---- online softmax ----
        int r0 = wm1 * 16 + gid, r1 = r0 + 8;
        float mx0 = -1e30f, mx1 = -1e30f;
#pragma unroll
        for (int nt = 0; nt < 4; nt++) {
            mx0 = fmaxf(mx0, fmaxf(s[nt][0], s[nt][1]));
            mx1 = fmaxf(mx1, fmaxf(s[nt][2], s[nt][3]));
        }
        mx0 = fmaxf(mx0, __shfl_xor_sync(0xffffffffu, mx0, 1));
        mx0 = fmaxf(mx0, __shfl_xor_sync(0xffffffffu, mx0, 2));
        mx1 = fmaxf(mx1, __shfl_xor_sync(0xffffffffu, mx1, 1));
        mx1 = fmaxf(mx1, __shfl_xor_sync(0xffffffffu, mx1, 2));
        if (tig == 0) { redm[r0 * 4 + wn1] = mx0; redm[r1 * 4 + wn1] = mx1; }
        __syncthreads();   // (A)

        float m_old0 = m_s[r0], m_old1 = m_s[r1];
        float mn0 = fmaxf(m_old0, fmaxf(redm[r0 * 4], redm[r0 * 4 + 1]));
        float mn1 = fmaxf(m_old1, fmaxf(redm[r1 * 4], redm[r1 * 4 + 1]));
        float s0 = 0.f, s1 = 0.f;
#pragma unroll
        for (int nt = 0; nt < 4; nt++) {
            float e0 = rna(__expf(s[nt][0] - mn0));
            float e1 = rna(__expf(s[nt][1] - mn0));
            float e2 = rna(__expf(s[nt][2] - mn1));
            float e3 = rna(__expf(s[nt][3] - mn1));
            s0 += e0 + e1; s1 += e2 + e3;
            int col = wn1 * 32 + nt * 8 + tig * 2;
            float2 w0; w0.x = e0; w0.y = e1;
            float2 w1; w1.x = e2; w1.y = e3;
            *(float2*)&Ps[r0 * PP + col] = w0;
            *(float2*)&Ps[r1 * PP + col] = w1;
        }
        s0 += __shfl_xor_sync(0xffffffffu, s0, 1);
        s0 += __shfl_xor_sync(0xffffffffu, s0, 2);
        s1 += __shfl_xor_sync(0xffffffffu, s1, 1);
        s1 += __shfl_xor_sync(0xffffffffu, s1, 2);
        if (tig == 0) { reds[r0 * 4 + wn1] = s0; reds[r1 * 4 + wn1] = s1; }

        // O rescale (gemm2 rows; m_s not yet updated)
        float al[2][2];
#pragma unroll
        for (int mt = 0; mt < 2; mt++) {
            int rr0 = wm2 * 32 + mt * 16 + gid, rr1 = rr0 + 8;
            float mo0 = m_s[rr0];
            float nn0 = fmaxf(mo0, fmaxf(redm[rr0 * 4], redm[rr0 * 4 + 1]));
            al[mt][0] = __expf(mo0 - nn0);
            float mo1 = m_s[rr1];
            float nn1 = fmaxf(mo1, fmaxf(redm[rr1 * 4], redm[rr1 * 4 + 1]));
            al[mt][1] = __expf(mo1 - nn1);
        }
#pragma unroll
        for (int mt = 0; mt < 2; mt++)
#pragma unroll
            for (int nt = 0; nt < 8; nt++) {
                oa[mt][nt][0] *= al[mt][0]; oa[mt][nt][1] *= al[mt][0];
                oa[mt][nt][2] *= al[mt][1]; oa[mt][nt][3] *= al[mt][1];
            }
        __syncthreads();   // (B): Ps, reds published

        // stats update (one writer per row)
        if (wn1 == 0 && tig == 0) {
            float t0 = reds[r0 * 4] + reds[r0 * 4 + 1];
            l_s[r0] = l_s[r0] * __expf(m_old0 - mn0) + t0;
            m_s[r0] = mn0;
            float t1 = reds[r1 * 4] + reds[r1 * 4 + 1];
            l_s[r1] = l_s[r1] * __expf(m_old1 - mn1) + t1;
            m_s[r1] = mn1;
        }

        if (t < 15) { CP_WAIT1; } else { CP_WAIT0; }   // V(t) complete
        __syncthreads();   // (C)

        // ---- gemm2: O(32x64 per warp) += P x V ----
#pragma unroll
        for (int k0 = 0; k0 < JT; k0 += 8) {
            uint32_t pa[2][4];
#pragma unroll
            for (int mt = 0; mt < 2; mt++) {
                const float* pp = &Ps[(wm2 * 32 + mt * 16 + gid) * PP + k0 + tig];
                pa[mt][0] = fb(pp[0]);
                pa[mt][1] = fb(pp[8 * PP]);
                pa[mt][2] = fb(pp[4]);
                pa[mt][3] = fb(pp[8 * PP + 4]);
            }
#pragma unroll
            for (int nt = 0; nt < 8; nt++) {
                const float* vp = &Vs[(wn2 * 64 + nt * 8 + gid) * VP + k0 + tig];
                uint32_t b0 = fb(vp[0]), b1 = fb(vp[4]);
#pragma unroll
                for (int mt = 0; mt < 2; mt++)
                    mma_tf32(oa[mt][nt], pa[mt][0], pa[mt][1], pa[mt][2], pa[mt][3], b0, b1);
            }
        }
    }

    __syncthreads();
    // epilogue: O/l + residual, round, store X'[i][c]
    float* Xb = X + ((size_t)b * NHW + i0) * NCQ;
    const float* qres = queryT + ((size_t)b * NHW + i0) * NCQ;
#pragma unroll
    for (int mt = 0; mt < 2; mt++) {
        int r0 = wm2 * 32 + mt * 16 + gid, r1 = r0 + 8;
        float inv0 = 1.f / l_s[r0], inv1 = 1.f / l_s[r1];
#pragma unroll
        for (int nt = 0; nt < 8; nt++) {
            int col = wn2 * 64 + nt * 8 + tig * 2;
            float2 q0 = *(const float2*)&qres[(size_t)r0 * NCQ + col];
            float2 q1 = *(const float2*)&qres[(size_t)r1 * NCQ + col];
            float2 o0, o1;
            o0.x = rna(oa[mt][nt][0] * inv0 + q0.x);
            o0.y = rna(oa[mt][nt][1] * inv0 + q0.y);
            o1.x = rna(oa[mt][nt][2] * inv1 + q1.x);
            o1.y = rna(oa[mt][nt][3] * inv1 + q1.y);
            *(float2*)&Xb[(size_t)r0 * NCQ + col] = o0;
            *(float2*)&Xb[(size_t)r1 * NCQ + col] = o1;
        }
    }
}

// ---------------- 7a. per-batch sum / sumsq of fused ----------------------------
__global__ void stats_kernel() {
    int b = blockIdx.x;
    const float* p = g_F + (size_t)b * GN_N;
    float s = 0.f, s2 = 0.f;
    for (int i = threadIdx.x; i < GN_N; i += blockDim.x) {
        float v = p[i]; s += v; s2 += v * v;
    }
    __shared__ float shs[32], shq[32];
#pragma unroll
    for (int o = 16; o; o >>= 1) {
        s  += __shfl_xor_sync(0xffffffffu, s, o);
        s2 += __shfl_xor_sync(0xffffffffu, s2, o);
    }
    int w = threadIdx.x >> 5;
    if ((threadIdx.x & 31) == 0) { shs[w] = s; shq[w] = s2; }
    __syncthreads();
    if (threadIdx.x < 32) {
        s = shs[threadIdx.x]; s2 = shq[threadIdx.x];
#pragma unroll
        for (int o = 16; o; o >>= 1) {
            s  += __shfl_xor_sync(0xffffffffu, s, o);
            s2 += __shfl_xor_sync(0xffffffffu, s2, o);
        }
        if (threadIdx.x == 0) { g_sums[b * 2] = s; g_sums[b * 2 + 1] = s2; }
    }
}

// ---------------- 7b. normalize + affine -> out ----------------------------------
__global__ void norm_kernel(const float* __restrict__ gamma, const float* __restrict__ beta,
                            float* __restrict__ out) {
    int idx = blockIdx.x * blockDim.x + threadIdx.x;
    int b = idx >> 18;
    int o = (idx >> 10) & 255;
    float s = g_sums[b * 2], s2 = g_sums[b * 2 + 1];
    const float n = (float)GN_N;
    float mu = s / n;
    float var = s2 / n - mu * mu;
    float rstd = rsqrtf(var + 1e-5f);
    out[idx] = (g_F[idx] - mu) * rstd * gamma[o] + beta[o];
}

// ---------------- launch ----------------------------------------------------------
extern "C" void kernel_launch(void* const* d_in, const int* in_sizes, int n_in,
                              void* d_out, int out_size) {
    const float* query = (const float*)d_in[0];
    const float* ctx   = (const float*)d_in[1];
    const float* Wq = (const float*)d_in[2];  const float* bq = (const float*)d_in[3];
    const float* Wk = (const float*)d_in[4];  const float* bk = (const float*)d_in[5];
    const float* Wv = (const float*)d_in[6];  const float* bv = (const float*)d_in[7];
    const float* Wp = (const float*)d_in[8];  const float* bp = (const float*)d_in[9];
    const float* gamma = (const float*)d_in[10];
    const float* beta  = (const float*)d_in[11];
    float* out = (float*)d_out;

    float *p_qT, *p_kT, *p_v, *p_X, *p_F, *p_queryT, *p_Wq, *p_Wp;
    cudaGetSymbolAddress((void**)&p_qT, g_qT);
    cudaGetSymbolAddress((void**)&p_kT, g_kT);
    cudaGetSymbolAddress((void**)&p_v, g_v);
    cudaGetSymbolAddress((void**)&p_X, g_X);
    cudaGetSymbolAddress((void**)&p_F, g_F);
    cudaGetSymbolAddress((void**)&p_queryT, g_queryT);
    cudaGetSymbolAddress((void**)&p_Wq, g_Wq);
    cudaGetSymbolAddress((void**)&p_Wp, g_Wp);

    static int smem_set = 0;
    if (!smem_set) {
        cudaFuncSetAttribute(flash_kernel, cudaFuncAttributeMaxDynamicSharedMemorySize,
                             SMEM_FLOATS * (int)sizeof(float));
        smem_set = 1;
    }

    // preprocessing
    resize_kernel<<<(NB * NHW + 255) / 256, 256>>>(ctx);
    prep_weights<<<256, 256>>>(Wq, Wp);
    transpose_round<<<dim3(NHW / 32, NCQ / 32, NB), dim3(32, 32)>>>(query);
    kproj_kernel<<<(NB * NHW * NINTER) / 256, 256>>>(Wk, bk);
    vproj_kernel<<<(NB * NCQ * NHW) / 256, 256>>>(Wv, bv);

    // 1. qT[i][c'] = queryT[i][c] x Wq[c'][c] + bq   (M=1024, N=128, K=256)
    gemm_tc<<<dim3(NINTER / 128, NHW / 128, NB), 256>>>(
        p_queryT, p_Wq, p_qT,
        (size_t)NHW * NCQ, 0, (size_t)NHW * NINTER,
        nullptr, bq, NHW, NINTER, NCQ, 1);

    // 2-4. fused flash attention -> X'[b][i][c] (with residual, rounded)
    flash_kernel<<<dim3(NHW / IT, NB), 256, SMEM_FLOATS * sizeof(float)>>>(
        p_qT, p_kT, p_v, p_queryT, p_X);

    // 5. F[o][i] = Wp[o][:] . X'[i][:] + bp[o]   (M=256, N=1024, K=256)
    gemm_tc<<<dim3(NHW / 128, NCQ / 128, NB), 256>>>(
        p_Wp, p_X, p_F,
        0, (size_t)NHW * NCQ, (size_t)NCQ * NHW,
        bp, nullptr, NCQ, NHW, NCQ, 0);

    // 6. group norm (1 group)
    stats_kernel<<<NB, 1024>>>();
    norm_kernel<<<(NB * NCQ * NHW) / 256, 256>>>(gamma, beta, out);
}

// round 4
// speedup vs baseline: 2.5647x; 1.1505x over previous
#include <cuda_runtime.h>
#include <math.h>
#include <stdint.h>

#define NB 32
#define NCQ 256
#define NCC 3
#define NINTER 128
#define NHW 1024
#define NHC 224
#define GN_N (NCQ*NHW)

// ---------------- scratch (static device memory, no allocs) ----------------
__device__ float g_qT[NB*NHW*NINTER];               // [b][i][c']  tf32-rounded
__device__ float g_kT[NB*NHW*NINTER];               // [b][j][c']  tf32-rounded
__device__ float g_v [NB*NCQ*NHW];                  // [b][c][j]   tf32-rounded
__device__ float g_X [NB*NHW*NCQ];                  // X'[b][i][c] (query+attended, rounded)
__device__ float g_F [NB*NCQ*NHW];                  // fused F[b][o][i] (fp32)
__device__ float g_queryT[NB*NHW*NCQ];              // [b][i][c]   tf32-rounded
__device__ float g_Wq[NINTER*NCQ];                  // rounded
__device__ float g_Wp[NCQ*NCQ];                     // rounded
__device__ float g_sums[NB*2];

__device__ __forceinline__ float rna(float x) {
    float r;
    asm("cvt.rna.tf32.f32 %0, %1;" : "=f"(r) : "f"(x));
    return r;
}
__device__ __forceinline__ uint32_t fb(float x) { return __float_as_uint(x); }

__device__ __forceinline__ void mma_tf32(float* d, uint32_t a0, uint32_t a1, uint32_t a2,
                                         uint32_t a3, uint32_t b0, uint32_t b1) {
    asm volatile(
        "mma.sync.aligned.m16n8k8.row.col.f32.tf32.tf32.f32 "
        "{%0,%1,%2,%3}, {%4,%5,%6,%7}, {%8,%9}, {%0,%1,%2,%3};"
        : "+f"(d[0]), "+f"(d[1]), "+f"(d[2]), "+f"(d[3])
        : "r"(a0), "r"(a1), "r"(a2), "r"(a3), "r"(b0), "r"(b1));
}

__device__ __forceinline__ void cpa16(float* dst, const float* src) {
    uint32_t d = (uint32_t)__cvta_generic_to_shared(dst);
    asm volatile("cp.async.cg.shared.global [%0], [%1], 16;" :: "r"(d), "l"(src));
}
#define CP_COMMIT asm volatile("cp.async.commit_group;")

// ---------------- fused resize + k/v projection -------------------------------
// block: (j-chunk of 64, batch). Computes bilinear ctx into smem, then k & v.
__global__ __launch_bounds__(256)
void proj_kernel(const float* __restrict__ ctx,
                 const float* __restrict__ Wk, const float* __restrict__ bk,
                 const float* __restrict__ Wv, const float* __restrict__ bv) {
    __shared__ float sctx[NCC][64];
    __shared__ float sWk[NINTER*3], sbk[NINTER];
    __shared__ float sWv[NCQ*3], sbv[NCQ];
    int tid = threadIdx.x;
    int b = blockIdx.y, j0 = blockIdx.x * 64;

    // weights to smem
    for (int i = tid; i < NINTER*3; i += 256) sWk[i] = Wk[i];
    for (int i = tid; i < NCQ*3; i += 256)    sWv[i] = Wv[i];
    if (tid < NINTER) sbk[tid] = bk[tid];
    if (tid < NCQ)    sbv[tid] = bv[tid];

    // bilinear for 3 channels x 64 positions
    if (tid < NCC * 64) {
        int c = tid >> 6, jj = tid & 63;
        int p = j0 + jj;
        int y = p >> 5, x = p & 31;
        float sy = 7.f * y + 3.f;
        float sx = 7.f * x + 3.f;
        int y0 = (int)floorf(sy), x0 = (int)floorf(sx);
        float fy = sy - y0, fx = sx - x0;
        int y1 = min(y0 + 1, NHC - 1), x1 = min(x0 + 1, NHC - 1);
        y0 = max(y0, 0); x0 = max(x0, 0);
        const float* base = ctx + ((size_t)b * NCC + c) * NHC * NHC;
        float v00 = base[y0 * NHC + x0], v01 = base[y0 * NHC + x1];
        float v10 = base[y1 * NHC + x0], v11 = base[y1 * NHC + x1];
        sctx[c][jj] = (1.f - fy) * ((1.f - fx) * v00 + fx * v01)
                    + fy * ((1.f - fx) * v10 + fx * v11);
    }
    __syncthreads();

    // k: [b][j][c'] (c contiguous)
    float* kout = g_kT + ((size_t)b * NHW + j0) * NINTER;
#pragma unroll 4
    for (int o = tid; o < 64 * NINTER; o += 256) {
        int jj = o >> 7, c = o & 127;
        kout[(size_t)jj * NINTER + c] =
            rna(sbk[c] + sWk[c*3]*sctx[0][jj] + sWk[c*3+1]*sctx[1][jj] + sWk[c*3+2]*sctx[2][jj]);
    }
    // v: [b][c][j] (j contiguous)
    float* vout = g_v + (size_t)b * NCQ * NHW + j0;
#pragma unroll 4
    for (int o = tid; o < NCQ * 64; o += 256) {
        int c = o >> 6, jj = o & 63;
        vout[(size_t)c * NHW + jj] =
            rna(sbv[c] + sWv[c*3]*sctx[0][jj] + sWv[c*3+1]*sctx[1][jj] + sWv[c*3+2]*sctx[2][jj]);
    }
}

// ---------------- queryT transpose + round ------------------------------------
__global__ void transpose_round(const float* __restrict__ in) {
    __shared__ float t[32][33];
    int b = blockIdx.z;
    int i0 = blockIdx.x * 32, c0 = blockIdx.y * 32;
    const float* ip = in + (size_t)b * NCQ * NHW;
    float* op = g_queryT + (size_t)b * NHW * NCQ;
    t[threadIdx.y][threadIdx.x] = ip[(size_t)(c0 + threadIdx.y) * NHW + i0 + threadIdx.x];
    __syncthreads();
    op[(size_t)(i0 + threadIdx.y) * NCQ + c0 + threadIdx.x] = rna(t[threadIdx.x][threadIdx.y]);
}

// ---------------- weight rounding + stats zero ----------------------------------
__global__ void prep_weights(const float* __restrict__ Wq, const float* __restrict__ Wp) {
    int i = blockIdx.x * blockDim.x + threadIdx.x;
    if (i < NINTER * NCQ) g_Wq[i] = rna(Wq[i]);
    if (i < NCQ * NCQ)    g_Wp[i] = rna(Wp[i]);
    if (i < NB * 2)       g_sums[i] = 0.f;
}

// ---------------- tf32 tensor-core ABT GEMM -------------------------------------
#define SMP 20
__global__ __launch_bounds__(256, 2)
void gemm_tc(const float* __restrict__ A, const float* __restrict__ B, float* __restrict__ C,
             size_t sA, size_t sB, size_t sC,
             const float* __restrict__ bias_m, const float* __restrict__ bias_n,
             int M, int N, int K, int roundOut, int doStats) {
    __shared__ float As[2][128 * SMP];
    __shared__ float Bs[2][128 * SMP];
    __shared__ float rs[8], rq[8];
    int b = blockIdx.z;
    A += (size_t)b * sA; B += (size_t)b * sB; C += (size_t)b * sC;
    int m0 = blockIdx.y * 128, n0 = blockIdx.x * 128;
    int tid = threadIdx.x, lane = tid & 31, wid = tid >> 5;
    int wm = wid >> 2, wn = wid & 3;
    int gid = lane >> 2, tig = lane & 3;

    float acc[4][4][4];
#pragma unroll
    for (int i = 0; i < 4; i++)
#pragma unroll
        for (int j = 0; j < 4; j++)
#pragma unroll
            for (int r = 0; r < 4; r++) acc[i][j][r] = 0.f;

    int lrow0 = tid >> 2,         lc4_0 = (tid & 3) * 4;
    int lrow1 = (tid + 256) >> 2, lc4_1 = lc4_0;
    int nk = K / 16;
    float4 ra0, ra1, rb0, rb1;

    ra0 = *(const float4*)&A[(size_t)(m0 + lrow0) * K + lc4_0];
    ra1 = *(const float4*)&A[(size_t)(m0 + lrow1) * K + lc4_1];
    rb0 = *(const float4*)&B[(size_t)(n0 + lrow0) * K + lc4_0];
    rb1 = *(const float4*)&B[(size_t)(n0 + lrow1) * K + lc4_1];
    {
        float* a = &As[0][lrow0 * SMP + lc4_0];
        a[0] = ra0.x; a[1] = ra0.y; a[2] = ra0.z; a[3] = ra0.w;
        a = &As[0][lrow1 * SMP + lc4_1];
        a[0] = ra1.x; a[1] = ra1.y; a[2] = ra1.z; a[3] = ra1.w;
        float* p = &Bs[0][lrow0 * SMP + lc4_0];
        p[0] = rb0.x; p[1] = rb0.y; p[2] = rb0.z; p[3] = rb0.w;
        p = &Bs[0][lrow1 * SMP + lc4_1];
        p[0] = rb1.x; p[1] = rb1.y; p[2] = rb1.z; p[3] = rb1.w;
    }
    __syncthreads();

    for (int kt = 0; kt < nk; kt++) {
        int cur = kt & 1;
        if (kt + 1 < nk) {
            int kb = (kt + 1) * 16;
            ra0 = *(const float4*)&A[(size_t)(m0 + lrow0) * K + kb + lc4_0];
            ra1 = *(const float4*)&A[(size_t)(m0 + lrow1) * K + kb + lc4_1];
            rb0 = *(const float4*)&B[(size_t)(n0 + lrow0) * K + kb + lc4_0];
            rb1 = *(const float4*)&B[(size_t)(n0 + lrow1) * K + kb + lc4_1];
        }
#pragma unroll
        for (int ks = 0; ks < 2; ks++) {
            int k0 = ks * 8;
            uint32_t afr[4][4], bfr[4][2];
#pragma unroll
            for (int mt = 0; mt < 4; mt++) {
                const float* ap = &As[cur][(wm * 64 + mt * 16 + gid) * SMP + k0 + tig];
                afr[mt][0] = fb(ap[0]);
                afr[mt][1] = fb(ap[8 * SMP]);
                afr[mt][2] = fb(ap[4]);
                afr[mt][3] = fb(ap[8 * SMP + 4]);
            }
#pragma unroll
            for (int nt = 0; nt < 4; nt++) {
                const float* bp = &Bs[cur][(wn * 32 + nt * 8 + gid) * SMP + k0 + tig];
                bfr[nt][0] = fb(bp[0]);
                bfr[nt][1] = fb(bp[4]);
            }
#pragma unroll
            for (int mt = 0; mt < 4; mt++)
#pragma unroll
                for (int nt = 0; nt < 4; nt++)
                    mma_tf32(acc[mt][nt], afr[mt][0], afr[mt][1], afr[mt][2], afr[mt][3],
                             bfr[nt][0], bfr[nt][1]);
        }
        if (kt + 1 < nk) {
            int nxt = cur ^ 1;
            float* a = &As[nxt][lrow0 * SMP + lc4_0];
            a[0] = ra0.x; a[1] = ra0.y; a[2] = ra0.z; a[3] = ra0.w;
            a = &As[nxt][lrow1 * SMP + lc4_1];
            a[0] = ra1.x; a[1] = ra1.y; a[2] = ra1.z; a[3] = ra1.w;
            float* p = &Bs[nxt][lrow0 * SMP + lc4_0];
            p[0] = rb0.x; p[1] = rb0.y; p[2] = rb0.z; p[3] = rb0.w;
            p = &Bs[nxt][lrow1 * SMP + lc4_1];
            p[0] = rb1.x; p[1] = rb1.y; p[2] = rb1.z; p[3] = rb1.w;
        }
        __syncthreads();
    }

    float ls = 0.f, lq = 0.f;
#pragma unroll
    for (int mt = 0; mt < 4; mt++) {
#pragma unroll
        for (int nt = 0; nt < 4; nt++) {
            int row0 = m0 + wm * 64 + mt * 16 + gid;
            int col  = n0 + wn * 32 + nt * 8 + tig * 2;
#pragma unroll
            for (int h = 0; h < 2; h++) {
                int row = row0 + h * 8;
                float x = acc[mt][nt][h * 2], y = acc[mt][nt][h * 2 + 1];
                if (bias_m) { float bm = bias_m[row]; x += bm; y += bm; }
                if (bias_n) { x += bias_n[col]; y += bias_n[col + 1]; }
                if (roundOut) { x = rna(x); y = rna(y); }
                if (doStats) { ls += x + y; lq += x * x + y * y; }
                float2 r; r.x = x; r.y = y;
                *(float2*)&C[(size_t)row * N + col] = r;
            }
        }
    }
    if (doStats) {
#pragma unroll
        for (int o = 16; o; o >>= 1) {
            ls += __shfl_xor_sync(0xffffffffu, ls, o);
            lq += __shfl_xor_sync(0xffffffffu, lq, o);
        }
        if (lane == 0) { rs[wid] = ls; rq[wid] = lq; }
        __syncthreads();
        if (tid == 0) {
            float ts = 0.f, tq = 0.f;
#pragma unroll
            for (int i = 0; i < 8; i++) { ts += rs[i]; tq += rq[i]; }
            atomicAdd(&g_sums[b * 2], ts);
            atomicAdd(&g_sums[b * 2 + 1], tq);
        }
    }
}

// ---------------- flash attention (no-max softmax): O = exp(q.kT) . v / l -------
#define IT 64
#define JT 64
#define QP 132
#define KP 132
#define VP 68
#define PP 68
#define SMEM_FLOATS (IT*QP + 2*JT*KP + NCQ*VP + IT*PP + IT*2)

__global__ __launch_bounds__(256, 1)
void flash_kernel(const float* __restrict__ qT, const float* __restrict__ kT,
                  const float* __restrict__ v, const float* __restrict__ queryT,
                  float* __restrict__ X) {
    extern __shared__ float sm[];
    float* Qs   = sm;                    // IT x QP
    float* Ks   = Qs + IT * QP;          // 2 x JT x KP
    float* Vs   = Ks + 2 * JT * KP;      // NCQ x VP
    float* Ps   = Vs + NCQ * VP;         // IT x PP
    float* reds = Ps + IT * PP;          // IT x 2

    int b = blockIdx.y, i0 = blockIdx.x * IT;
    const float* qTb = qT + ((size_t)b * NHW + i0) * NINTER;
    const float* kTb = kT + (size_t)b * NHW * NINTER;
    const float* vb  = v  + (size_t)b * NCQ * NHW;

    int tid = threadIdx.x, lane = tid & 31, w = tid >> 5;
    int gid = lane >> 2, tig = lane & 3;
    int wm1 = w >> 1, wn1 = w & 1;        // gemm1: 4(m) x 2(n), warp tile 16x32
    int wm2 = w >> 2, wn2 = w & 3;        // gemm2: 2(m) x 4(n), warp tile 32x64

    // load Q tile (64 x 128)
#pragma unroll
    for (int it = 0; it < 8; it++) {
        int id = tid + it * 256;
        int r = id >> 5, c4 = (id & 31) * 4;
        *(float4*)&Qs[r * QP + c4] = *(const float4*)&qTb[(size_t)r * NINTER + c4];
    }

    // prologue: prefetch K0, V0
#pragma unroll
    for (int it = 0; it < 8; it++) {
        int id = tid + it * 256;
        int r = id >> 5, c = (id & 31) * 4;
        cpa16(&Ks[r * KP + c], &kTb[(size_t)r * NINTER + c]);
    }
    CP_COMMIT;
#pragma unroll
    for (int it = 0; it < 16; it++) {
        int id = tid + it * 256;
        int r = id >> 4, c = (id & 15) * 4;
        cpa16(&Vs[r * VP + c], &vb[(size_t)r * NHW + c]);
    }
    CP_COMMIT;

    float oa[2][8][4];
#pragma unroll
    for (int mt = 0; mt < 2; mt++)
#pragma unroll
        for (int nt = 0; nt < 8; nt++)
#pragma unroll
            for (int r = 0; r < 4; r++) oa[mt][nt][r] = 0.f;
    float lp0 = 0.f, lp1 = 0.f;
    int r0 = wm1 * 16 + gid, r1 = r0 + 8;

    for (int t = 0; t < 16; t++) {
        int buf = t & 1;
        __syncthreads();        // Vs/Ps free (gemm2(t-1) done); Ks[buf^1] free
        if (t > 0) {            // prefetch V(t)
            int j0 = t * JT;
#pragma unroll
            for (int it = 0; it < 16; it++) {
                int id = tid + it * 256;
                int r = id >> 4, c = (id & 15) * 4;
                cpa16(&Vs[r * VP + c], &vb[(size_t)r * NHW + j0 + c]);
            }
            CP_COMMIT;
        }
        if (t < 15) {           // prefetch K(t+1)
            int j0 = (t + 1) * JT;
            float* kd = &Ks[(buf ^ 1) * JT * KP];
#pragma unroll
            for (int it = 0; it < 8; it++) {
                int id = tid + it * 256;
                int r = id >> 5, c = (id & 31) * 4;
                cpa16(&kd[r * KP + c], &kTb[(size_t)(j0 + r) * NINTER + c]);
            }
            CP_COMMIT;
        }
        // wait K(t): pending = [K(t), V(t), K(t+1)] (subset at edges)
        if (t == 15) { asm volatile("cp.async.wait_group 1;"); }
        else         { asm volatile("cp.async.wait_group 2;"); }
        __syncthreads();

        // ---- gemm1: S(16x32 per warp) = Q x K^T ----
        float s[4][4];
#pragma unroll
        for (int nt = 0; nt < 4; nt++)
#pragma unroll
            for (int r = 0; r < 4; r++) s[nt][r] = 0.f;
        {
            const float* qp = &Qs[r0 * QP + tig];
            const float* kp = &Ks[buf * JT * KP + (wn1 * 32 + gid) * KP + tig];
#pragma unroll
            for (int k0 = 0; k0 < NINTER; k0 += 8) {
                uint32_t a0 = fb(qp[k0]), a1 = fb(qp[8 * QP + k0]);
                uint32_t a2 = fb(qp[k0 + 4]), a3 = fb(qp[8 * QP + k0 + 4]);
                uint32_t b0[4], b1[4];
#pragma unroll
                for (int nt = 0; nt < 4; nt++) {
                    b0[nt] = fb(kp[nt * 8 * KP + k0]);
                    b1[nt] = fb(kp[nt * 8 * KP + k0 + 4]);
                }
#pragma unroll
                for (int nt = 0; nt < 4; nt++)
                    mma_tf32(s[nt], a0, a1, a2, a3, b0[nt], b1[nt]);
            }
        }

        // ---- exp (no max subtraction) + write P + accumulate row sums ----
#pragma unroll
        for (int nt = 0; nt < 4; nt++) {
            float e0 = rna(__expf(s[nt][0]));
            float e1 = rna(__expf(s[nt][1]));
            float e2 = rna(__expf(s[nt][2]));
            float e3 = rna(__expf(s[nt][3]));
            lp0 += e0 + e1; lp1 += e2 + e3;
            int col = wn1 * 32 + nt * 8 + tig * 2;
            float2 w0; w0.x = e0; w0.y = e1;
            float2 w1; w1.x = e2; w1.y = e3;
            *(float2*)&Ps[r0 * PP + col] = w0;
            *(float2*)&Ps[r1 * PP + col] = w1;
        }

        // wait V(t): pending = [V(t), K(t+1)] (t=15: just V)
        if (t == 15) { asm volatile("cp.async.wait_group 0;"); }
        else         { asm volatile("cp.async.wait_group 1;"); }
        __syncthreads();        // Ps & Vs visible

        // ---- gemm2: O(32x64 per warp) += P x V ----
#pragma unroll
        for (int k0 = 0; k0 < JT; k0 += 8) {
            uint32_t pa[2][4];
#pragma unroll
            for (int mt = 0; mt < 2; mt++) {
                const float* pp = &Ps[(wm2 * 32 + mt * 16 + gid) * PP + k0 + tig];
                pa[mt][0] = fb(pp[0]);
                pa[mt][1] = fb(pp[8 * PP]);
                pa[mt][2] = fb(pp[4]);
                pa[mt][3] = fb(pp[8 * PP + 4]);
            }
            uint32_t vb0[8], vb1[8];
#pragma unroll
            for (int nt = 0; nt < 8; nt++) {
                const float* vp = &Vs[(wn2 * 64 + nt * 8 + gid) * VP + k0 + tig];
                vb0[nt] = fb(vp[0]); vb1[nt] = fb(vp[4]);
            }
#pragma unroll
            for (int nt = 0; nt < 8; nt++)
#pragma unroll
                for (int mt = 0; mt < 2; mt++)
                    mma_tf32(oa[mt][nt], pa[mt][0], pa[mt][1], pa[mt][2], pa[mt][3],
                             vb0[nt], vb1[nt]);
        }
    }

    // final row-sum reduction: quad shuffle then combine the two warp-halves
    lp0 += __shfl_xor_sync(0xffffffffu, lp0, 1);
    lp0 += __shfl_xor_sync(0xffffffffu, lp0, 2);
    lp1 += __shfl_xor_sync(0xffffffffu, lp1, 1);
    lp1 += __shfl_xor_sync(0xffffffffu, lp1, 2);
    if (tig == 0) { reds[r0 * 2 + wn1] = lp0; reds[r1 * 2 + wn1] = lp1; }
    __syncthreads();

    // epilogue: O/l + residual, round, store X'[i][c]
    float* Xb = X + ((size_t)b * NHW + i0) * NCQ;
    const float* qres = queryT + ((size_t)b * NHW + i0) * NCQ;
#pragma unroll
    for (int mt = 0; mt < 2; mt++) {
        int rr0 = wm2 * 32 + mt * 16 + gid, rr1 = rr0 + 8;
        float inv0 = 1.f / (reds[rr0 * 2] + reds[rr0 * 2 + 1]);
        float inv1 = 1.f / (reds[rr1 * 2] + reds[rr1 * 2 + 1]);
#pragma unroll
        for (int nt = 0; nt < 8; nt++) {
            int col = wn2 * 64 + nt * 8 + tig * 2;
            float2 q0 = *(const float2*)&qres[(size_t)rr0 * NCQ + col];
            float2 q1 = *(const float2*)&qres[(size_t)rr1 * NCQ + col];
            float2 o0, o1;
            o0.x = rna(oa[mt][nt][0] * inv0 + q0.x);
            o0.y = rna(oa[mt][nt][1] * inv0 + q0.y);
            o1.x = rna(oa[mt][nt][2] * inv1 + q1.x);
            o1.y = rna(oa[mt][nt][3] * inv1 + q1.y);
            *(float2*)&Xb[(size_t)rr0 * NCQ + col] = o0;
            *(float2*)&Xb[(size_t)rr1 * NCQ + col] = o1;
        }
    }
}

// ---------------- normalize + affine -> out --------------------------------------
__global__ void norm_kernel(const float* __restrict__ gamma, const float* __restrict__ beta,
                            float* __restrict__ out) {
    int idx = blockIdx.x * blockDim.x + threadIdx.x;
    int b = idx >> 18;
    int o = (idx >> 10) & 255;
    float s = g_sums[b * 2], s2 = g_sums[b * 2 + 1];
    const float n = (float)GN_N;
    float mu = s / n;
    float var = s2 / n - mu * mu;
    float rstd = rsqrtf(var + 1e-5f);
    out[idx] = (g_F[idx] - mu) * rstd * gamma[o] + beta[o];
}

// ---------------- launch -----------------------------------------------------------
extern "C" void kernel_launch(void* const* d_in, const int* in_sizes, int n_in,
                              void* d_out, int out_size) {
    const float* query = (const float*)d_in[0];
    const float* ctx   = (const float*)d_in[1];
    const float* Wq = (const float*)d_in[2];  const float* bq = (const float*)d_in[3];
    const float* Wk = (const float*)d_in[4];  const float* bk = (const float*)d_in[5];
    const float* Wv = (const float*)d_in[6];  const float* bv = (const float*)d_in[7];
    const float* Wp = (const float*)d_in[8];  const float* bp = (const float*)d_in[9];
    const float* gamma = (const float*)d_in[10];
    const float* beta  = (const float*)d_in[11];
    float* out = (float*)d_out;

    float *p_qT, *p_kT, *p_v, *p_X, *p_F, *p_queryT, *p_Wq, *p_Wp;
    cudaGetSymbolAddress((void**)&p_qT, g_qT);
    cudaGetSymbolAddress((void**)&p_kT, g_kT);
    cudaGetSymbolAddress((void**)&p_v, g_v);
    cudaGetSymbolAddress((void**)&p_X, g_X);
    cudaGetSymbolAddress((void**)&p_F, g_F);
    cudaGetSymbolAddress((void**)&p_queryT, g_queryT);
    cudaGetSymbolAddress((void**)&p_Wq, g_Wq);
    cudaGetSymbolAddress((void**)&p_Wp, g_Wp);

    static int smem_set = 0;
    if (!smem_set) {
        cudaFuncSetAttribute(flash_kernel, cudaFuncAttributeMaxDynamicSharedMemorySize,
                             SMEM_FLOATS * (int)sizeof(float));
        smem_set = 1;
    }

    // preprocessing (fused projections + transpose + weight prep/zero)
    prep_weights<<<256, 256>>>(Wq, Wp);
    proj_kernel<<<dim3(NHW / 64, NB), 256>>>(ctx, Wk, bk, Wv, bv);
    transpose_round<<<dim3(NHW / 32, NCQ / 32, NB), dim3(32, 32)>>>(query);

    // q projection: qT[i][c'] = queryT[i][c] x Wq[c'][c] + bq
    gemm_tc<<<dim3(NINTER / 128, NHW / 128, NB), 256>>>(
        p_queryT, p_Wq, p_qT,
        (size_t)NHW * NCQ, 0, (size_t)NHW * NINTER,
        nullptr, bq, NHW, NINTER, NCQ, 1, 0);

    // flash attention -> X'[b][i][c] (with residual, rounded)
    flash_kernel<<<dim3(NHW / IT, NB), 256, SMEM_FLOATS * sizeof(float)>>>(
        p_qT, p_kT, p_v, p_queryT, p_X);

    // fused conv: F[o][i] = Wp[o][:] . X'[i][:] + bp[o]   (+ GN stats via atomics)
    gemm_tc<<<dim3(NHW / 128, NCQ / 128, NB), 256>>>(
        p_Wp, p_X, p_F,
        0, (size_t)NHW * NCQ, (size_t)NCQ * NHW,
        bp, nullptr, NCQ, NHW, NCQ, 0, 1);

    // group norm apply
    norm_kernel<<<(NB * NCQ * NHW) / 256, 256>>>(gamma, beta, out);
}

// round 5
// speedup vs baseline: 3.1584x; 1.2315x over previous
#include <cuda_runtime.h>
#include <math.h>
#include <stdint.h>

#define NB 32
#define NCQ 256
#define NCC 3
#define NINTER 128
#define NHW 1024
#define NHC 224
#define GN_N (NCQ*NHW)

// ---------------- scratch (static device memory, no allocs) ----------------
__device__ float g_qT[NB*NHW*NINTER];               // [b][i][c']  tf32-rounded
__device__ float g_kT[NB*NHW*NINTER];               // [b][j][c']  tf32-rounded
__device__ float g_v [NB*NCQ*NHW];                  // [b][c][j]   tf32-rounded
__device__ float g_X [NB*NHW*NCQ];                  // X'[b][i][c] (query+attended, rounded)
__device__ float g_F [NB*NCQ*NHW];                  // fused F[b][o][i] (fp32)
__device__ float g_queryT[NB*NHW*NCQ];              // [b][i][c]   tf32-rounded
__device__ float g_Wq[NINTER*NCQ];                  // rounded
__device__ float g_Wp[NCQ*NCQ];                     // rounded
__device__ float g_sums[NB*2];

__device__ __forceinline__ float rna(float x) {
    float r;
    asm("cvt.rna.tf32.f32 %0, %1;" : "=f"(r) : "f"(x));
    return r;
}
__device__ __forceinline__ uint32_t fb(float x) { return __float_as_uint(x); }

__device__ __forceinline__ void mma_tf32(float* d, uint32_t a0, uint32_t a1, uint32_t a2,
                                         uint32_t a3, uint32_t b0, uint32_t b1) {
    asm volatile(
        "mma.sync.aligned.m16n8k8.row.col.f32.tf32.tf32.f32 "
        "{%0,%1,%2,%3}, {%4,%5,%6,%7}, {%8,%9}, {%0,%1,%2,%3};"
        : "+f"(d[0]), "+f"(d[1]), "+f"(d[2]), "+f"(d[3])
        : "r"(a0), "r"(a1), "r"(a2), "r"(a3), "r"(b0), "r"(b1));
}

__device__ __forceinline__ void cpa16(float* dst, const float* src) {
    uint32_t d = (uint32_t)__cvta_generic_to_shared(dst);
    asm volatile("cp.async.cg.shared.global [%0], [%1], 16;" :: "r"(d), "l"(src));
}
#define CP_COMMIT asm volatile("cp.async.commit_group;")

// ---------------- fused resize + k/v projection -------------------------------
__global__ __launch_bounds__(256)
void proj_kernel(const float* __restrict__ ctx,
                 const float* __restrict__ Wk, const float* __restrict__ bk,
                 const float* __restrict__ Wv, const float* __restrict__ bv) {
    __shared__ float sctx[NCC][64];
    __shared__ float sWk[NINTER*3], sbk[NINTER];
    __shared__ float sWv[NCQ*3], sbv[NCQ];
    int tid = threadIdx.x;
    int b = blockIdx.y, j0 = blockIdx.x * 64;

    for (int i = tid; i < NINTER*3; i += 256) sWk[i] = Wk[i];
    for (int i = tid; i < NCQ*3; i += 256)    sWv[i] = Wv[i];
    if (tid < NINTER) sbk[tid] = bk[tid];
    if (tid < NCQ)    sbv[tid] = bv[tid];

    if (tid < NCC * 64) {
        int c = tid >> 6, jj = tid & 63;
        int p = j0 + jj;
        int y = p >> 5, x = p & 31;
        float sy = 7.f * y + 3.f;
        float sx = 7.f * x + 3.f;
        int y0 = (int)floorf(sy), x0 = (int)floorf(sx);
        float fy = sy - y0, fx = sx - x0;
        int y1 = min(y0 + 1, NHC - 1), x1 = min(x0 + 1, NHC - 1);
        y0 = max(y0, 0); x0 = max(x0, 0);
        const float* base = ctx + ((size_t)b * NCC + c) * NHC * NHC;
        float v00 = base[y0 * NHC + x0], v01 = base[y0 * NHC + x1];
        float v10 = base[y1 * NHC + x0], v11 = base[y1 * NHC + x1];
        sctx[c][jj] = (1.f - fy) * ((1.f - fx) * v00 + fx * v01)
                    + fy * ((1.f - fx) * v10 + fx * v11);
    }
    __syncthreads();

    float* kout = g_kT + ((size_t)b * NHW + j0) * NINTER;
#pragma unroll 4
    for (int o = tid; o < 64 * NINTER; o += 256) {
        int jj = o >> 7, c = o & 127;
        kout[(size_t)jj * NINTER + c] =
            rna(sbk[c] + sWk[c*3]*sctx[0][jj] + sWk[c*3+1]*sctx[1][jj] + sWk[c*3+2]*sctx[2][jj]);
    }
    float* vout = g_v + (size_t)b * NCQ * NHW + j0;
#pragma unroll 4
    for (int o = tid; o < NCQ * 64; o += 256) {
        int c = o >> 6, jj = o & 63;
        vout[(size_t)c * NHW + jj] =
            rna(sbv[c] + sWv[c*3]*sctx[0][jj] + sWv[c*3+1]*sctx[1][jj] + sWv[c*3+2]*sctx[2][jj]);
    }
}

// ---------------- queryT transpose + round ------------------------------------
__global__ void transpose_round(const float* __restrict__ in) {
    __shared__ float t[32][33];
    int b = blockIdx.z;
    int i0 = blockIdx.x * 32, c0 = blockIdx.y * 32;
    const float* ip = in + (size_t)b * NCQ * NHW;
    float* op = g_queryT + (size_t)b * NHW * NCQ;
    t[threadIdx.y][threadIdx.x] = ip[(size_t)(c0 + threadIdx.y) * NHW + i0 + threadIdx.x];
    __syncthreads();
    op[(size_t)(i0 + threadIdx.y) * NCQ + c0 + threadIdx.x] = rna(t[threadIdx.x][threadIdx.y]);
}

// ---------------- weight rounding + stats zero ----------------------------------
__global__ void prep_weights(const float* __restrict__ Wq, const float* __restrict__ Wp) {
    int i = blockIdx.x * blockDim.x + threadIdx.x;
    if (i < NINTER * NCQ) g_Wq[i] = rna(Wq[i]);
    if (i < NCQ * NCQ)    g_Wp[i] = rna(Wp[i]);
    if (i < NB * 2)       g_sums[i] = 0.f;
}

// ---------------- tf32 tensor-core ABT GEMM -------------------------------------
#define SMP 20
__global__ __launch_bounds__(256, 2)
void gemm_tc(const float* __restrict__ A, const float* __restrict__ B, float* __restrict__ C,
             size_t sA, size_t sB, size_t sC,
             const float* __restrict__ bias_m, const float* __restrict__ bias_n,
             int M, int N, int K, int roundOut, int doStats) {
    __shared__ float As[2][128 * SMP];
    __shared__ float Bs[2][128 * SMP];
    __shared__ float rs[8], rq[8];
    int b = blockIdx.z;
    A += (size_t)b * sA; B += (size_t)b * sB; C += (size_t)b * sC;
    int m0 = blockIdx.y * 128, n0 = blockIdx.x * 128;
    int tid = threadIdx.x, lane = tid & 31, wid = tid >> 5;
    int wm = wid >> 2, wn = wid & 3;
    int gid = lane >> 2, tig = lane & 3;

    float acc[4][4][4];
#pragma unroll
    for (int i = 0; i < 4; i++)
#pragma unroll
        for (int j = 0; j < 4; j++)
#pragma unroll
            for (int r = 0; r < 4; r++) acc[i][j][r] = 0.f;

    int lrow0 = tid >> 2,         lc4_0 = (tid & 3) * 4;
    int lrow1 = (tid + 256) >> 2, lc4_1 = lc4_0;
    int nk = K / 16;
    float4 ra0, ra1, rb0, rb1;

    ra0 = *(const float4*)&A[(size_t)(m0 + lrow0) * K + lc4_0];
    ra1 = *(const float4*)&A[(size_t)(m0 + lrow1) * K + lc4_1];
    rb0 = *(const float4*)&B[(size_t)(n0 + lrow0) * K + lc4_0];
    rb1 = *(const float4*)&B[(size_t)(n0 + lrow1) * K + lc4_1];
    {
        float* a = &As[0][lrow0 * SMP + lc4_0];
        a[0] = ra0.x; a[1] = ra0.y; a[2] = ra0.z; a[3] = ra0.w;
        a = &As[0][lrow1 * SMP + lc4_1];
        a[0] = ra1.x; a[1] = ra1.y; a[2] = ra1.z; a[3] = ra1.w;
        float* p = &Bs[0][lrow0 * SMP + lc4_0];
        p[0] = rb0.x; p[1] = rb0.y; p[2] = rb0.z; p[3] = rb0.w;
        p = &Bs[0][lrow1 * SMP + lc4_1];
        p[0] = rb1.x; p[1] = rb1.y; p[2] = rb1.z; p[3] = rb1.w;
    }
    __syncthreads();

    for (int kt = 0; kt < nk; kt++) {
        int cur = kt & 1;
        if (kt + 1 < nk) {
            int kb = (kt + 1) * 16;
            ra0 = *(const float4*)&A[(size_t)(m0 + lrow0) * K + kb + lc4_0];
            ra1 = *(const float4*)&A[(size_t)(m0 + lrow1) * K + kb + lc4_1];
            rb0 = *(const float4*)&B[(size_t)(n0 + lrow0) * K + kb + lc4_0];
            rb1 = *(const float4*)&B[(size_t)(n0 + lrow1) * K + kb + lc4_1];
        }
#pragma unroll
        for (int ks = 0; ks < 2; ks++) {
            int k0 = ks * 8;
            uint32_t afr[4][4], bfr[4][2];
#pragma unroll
            for (int mt = 0; mt < 4; mt++) {
                const float* ap = &As[cur][(wm * 64 + mt * 16 + gid) * SMP + k0 + tig];
                afr[mt][0] = fb(ap[0]);
                afr[mt][1] = fb(ap[8 * SMP]);
                afr[mt][2] = fb(ap[4]);
                afr[mt][3] = fb(ap[8 * SMP + 4]);
            }
#pragma unroll
            for (int nt = 0; nt < 4; nt++) {
                const float* bp = &Bs[cur][(wn * 32 + nt * 8 + gid) * SMP + k0 + tig];
                bfr[nt][0] = fb(bp[0]);
                bfr[nt][1] = fb(bp[4]);
            }
#pragma unroll
            for (int mt = 0; mt < 4; mt++)
#pragma unroll
                for (int nt = 0; nt < 4; nt++)
                    mma_tf32(acc[mt][nt], afr[mt][0], afr[mt][1], afr[mt][2], afr[mt][3],
                             bfr[nt][0], bfr[nt][1]);
        }
        if (kt + 1 < nk) {
            int nxt = cur ^ 1;
            float* a = &As[nxt][lrow0 * SMP + lc4_0];
            a[0] = ra0.x; a[1] = ra0.y; a[2] = ra0.z; a[3] = ra0.w;
            a = &As[nxt][lrow1 * SMP + lc4_1];
            a[0] = ra1.x; a[1] = ra1.y; a[2] = ra1.z; a[3] = ra1.w;
            float* p = &Bs[nxt][lrow0 * SMP + lc4_0];
            p[0] = rb0.x; p[1] = rb0.y; p[2] = rb0.z; p[3] = rb0.w;
            p = &Bs[nxt][lrow1 * SMP + lc4_1];
            p[0] = rb1.x; p[1] = rb1.y; p[2] = rb1.z; p[3] = rb1.w;
        }
        __syncthreads();
    }

    float ls = 0.f, lq = 0.f;
#pragma unroll
    for (int mt = 0; mt < 4; mt++) {
#pragma unroll
        for (int nt = 0; nt < 4; nt++) {
            int row0 = m0 + wm * 64 + mt * 16 + gid;
            int col  = n0 + wn * 32 + nt * 8 + tig * 2;
#pragma unroll
            for (int h = 0; h < 2; h++) {
                int row = row0 + h * 8;
                float x = acc[mt][nt][h * 2], y = acc[mt][nt][h * 2 + 1];
                if (bias_m) { float bm = bias_m[row]; x += bm; y += bm; }
                if (bias_n) { x += bias_n[col]; y += bias_n[col + 1]; }
                if (roundOut) { x = rna(x); y = rna(y); }
                if (doStats) { ls += x + y; lq += x * x + y * y; }
                float2 r; r.x = x; r.y = y;
                *(float2*)&C[(size_t)row * N + col] = r;
            }
        }
    }
    if (doStats) {
#pragma unroll
        for (int o = 16; o; o >>= 1) {
            ls += __shfl_xor_sync(0xffffffffu, ls, o);
            lq += __shfl_xor_sync(0xffffffffu, lq, o);
        }
        if (lane == 0) { rs[wid] = ls; rq[wid] = lq; }
        __syncthreads();
        if (tid == 0) {
            float ts = 0.f, tq = 0.f;
#pragma unroll
            for (int i = 0; i < 8; i++) { ts += rs[i]; tq += rq[i]; }
            atomicAdd(&g_sums[b * 2], ts);
            atomicAdd(&g_sums[b * 2 + 1], tq);
        }
    }
}

// ---------------- flash attention v2: IT=128, 512 threads, swizzled smem --------
// O = exp(q.kT) . v / rowsum, +residual. grid: (NHW/128, NB).
// smem: Qs 128x128, Ks 2x64x128, Vs 256x64, Ps 128x64, reds 256  = 230400 B
#define F_SMEM_FLOATS (128*128 + 2*64*128 + 256*64 + 128*64 + 256)

__global__ __launch_bounds__(512, 1)
void flash_kernel(const float* __restrict__ qT, const float* __restrict__ kT,
                  const float* __restrict__ v, const float* __restrict__ queryT,
                  float* __restrict__ X) {
    extern __shared__ float sm[];
    float* Qs   = sm;                      // 128 x 128 (swizzled)
    float* Ks   = Qs + 128 * 128;          // 2 x 64 x 128 (swizzled)
    float* Vs   = Ks + 2 * 64 * 128;       // 256 x 64 (swizzled)
    float* Ps   = Vs + 256 * 64;           // 128 x 64 (swizzled)
    float* reds = Ps + 128 * 64;           // 128 x 2

    int b = blockIdx.y, i0 = blockIdx.x * 128;
    const float* qTb = qT + ((size_t)b * NHW + i0) * NINTER;
    const float* kTb = kT + (size_t)b * NHW * NINTER;
    const float* vb  = v  + (size_t)b * NCQ * NHW;

    int tid = threadIdx.x, lane = tid & 31, w = tid >> 5;
    int gid = lane >> 2, tig = lane & 3;
    int wm1 = w >> 1, wn1 = w & 1;         // gemm1: 8(m) x 2(n), warp tile 16x32
    int wm2 = w >> 2, wn2 = w & 3;         // gemm2: 4(m) x 4(n), warp tile 32x64
    int qm = gid << 2;                     // swizzle mask (row&7 == gid at all read sites)

    // load Q tile 128x128 (swizzled float4 stores)
#pragma unroll
    for (int it = 0; it < 8; it++) {
        int id = tid + it * 512;
        int r = id >> 5, c4 = (id & 31) << 2;
        float4 vq = *(const float4*)&qTb[(size_t)r * NINTER + c4];
        *(float4*)&Qs[r * 128 + (c4 ^ ((r & 7) << 2))] = vq;
    }

    // prologue: prefetch K0 (group), V0 (group)
#pragma unroll
    for (int it = 0; it < 4; it++) {
        int id = tid + it * 512;
        int r = id >> 5, c4 = (id & 31) << 2;
        cpa16(&Ks[r * 128 + (c4 ^ ((r & 7) << 2))], &kTb[(size_t)r * NINTER + c4]);
    }
    CP_COMMIT;
#pragma unroll
    for (int it = 0; it < 8; it++) {
        int id = tid + it * 512;
        int r = id >> 4, c4 = (id & 15) << 2;
        cpa16(&Vs[r * 64 + (c4 ^ ((r & 7) << 2))], &vb[(size_t)r * NHW + c4]);
    }
    CP_COMMIT;

    float oa[2][8][4];
#pragma unroll
    for (int mt = 0; mt < 2; mt++)
#pragma unroll
        for (int nt = 0; nt < 8; nt++)
#pragma unroll
            for (int r = 0; r < 4; r++) oa[mt][nt][r] = 0.f;
    float lp0 = 0.f, lp1 = 0.f;
    int r0 = wm1 * 16 + gid, r1 = r0 + 8;

    for (int t = 0; t < 16; t++) {
        int buf = t & 1;
        __syncthreads();        // gemm2(t-1) done: Vs/Ps free; Ks[buf^1] free
        if (t > 0) {            // prefetch V(t)
            int j0 = t * 64;
#pragma unroll
            for (int it = 0; it < 8; it++) {
                int id = tid + it * 512;
                int r = id >> 4, c4 = (id & 15) << 2;
                cpa16(&Vs[r * 64 + (c4 ^ ((r & 7) << 2))], &vb[(size_t)r * NHW + j0 + c4]);
            }
            CP_COMMIT;
        }
        if (t < 15) {           // prefetch K(t+1)
            int j0 = (t + 1) * 64;
            float* kd = &Ks[(buf ^ 1) * 64 * 128];
#pragma unroll
            for (int it = 0; it < 4; it++) {
                int id = tid + it * 512;
                int r = id >> 5, c4 = (id & 31) << 2;
                cpa16(&kd[r * 128 + (c4 ^ ((r & 7) << 2))], &kTb[(size_t)(j0 + r) * NINTER + c4]);
            }
            CP_COMMIT;
        }
        if (t == 15) { asm volatile("cp.async.wait_group 1;"); }
        else         { asm volatile("cp.async.wait_group 2;"); }
        __syncthreads();        // K(t) visible

        // ---- gemm1: S(16x32 per warp) = Q x K^T ----
        float s[4][4];
#pragma unroll
        for (int nt = 0; nt < 4; nt++)
#pragma unroll
            for (int r = 0; r < 4; r++) s[nt][r] = 0.f;
        {
            const float* qp = &Qs[r0 * 128];
            const float* kp = &Ks[buf * 64 * 128 + (wn1 * 32 + gid) * 128];
#pragma unroll
            for (int k0 = 0; k0 < NINTER; k0 += 8) {
                int cl = (k0 + tig) ^ qm, ch = (k0 + 4 + tig) ^ qm;
                uint32_t a0 = fb(qp[cl]), a1 = fb(qp[8 * 128 + cl]);
                uint32_t a2 = fb(qp[ch]), a3 = fb(qp[8 * 128 + ch]);
                uint32_t b0[4], b1[4];
#pragma unroll
                for (int nt = 0; nt < 4; nt++) {
                    b0[nt] = fb(kp[nt * 8 * 128 + cl]);
                    b1[nt] = fb(kp[nt * 8 * 128 + ch]);
                }
#pragma unroll
                for (int nt = 0; nt < 4; nt++)
                    mma_tf32(s[nt], a0, a1, a2, a3, b0[nt], b1[nt]);
            }
        }

        // ---- exp (no max subtraction) + write P (swizzled) + row-sum ----
#pragma unroll
        for (int nt = 0; nt < 4; nt++) {
            float e0 = rna(__expf(s[nt][0]));
            float e1 = rna(__expf(s[nt][1]));
            float e2 = rna(__expf(s[nt][2]));
            float e3 = rna(__expf(s[nt][3]));
            lp0 += e0 + e1; lp1 += e2 + e3;
            int col = (wn1 * 32 + nt * 8 + tig * 2) ^ qm;
            float2 w0; w0.x = e0; w0.y = e1;
            float2 w1; w1.x = e2; w1.y = e3;
            *(float2*)&Ps[r0 * 64 + col] = w0;
            *(float2*)&Ps[r1 * 64 + col] = w1;
        }

        if (t == 15) { asm volatile("cp.async.wait_group 0;"); }
        else         { asm volatile("cp.async.wait_group 1;"); }
        __syncthreads();        // Ps + V(t) visible

        // ---- gemm2: O(32x64 per warp) += P x V ----
#pragma unroll
        for (int k0 = 0; k0 < 64; k0 += 8) {
            int cl = (k0 + tig) ^ qm, ch = (k0 + 4 + tig) ^ qm;
            uint32_t pa[2][4];
#pragma unroll
            for (int mt = 0; mt < 2; mt++) {
                const float* pp = &Ps[(wm2 * 32 + mt * 16 + gid) * 64];
                pa[mt][0] = fb(pp[cl]);
                pa[mt][1] = fb(pp[8 * 64 + cl]);
                pa[mt][2] = fb(pp[ch]);
                pa[mt][3] = fb(pp[8 * 64 + ch]);
            }
            uint32_t vb0[8], vb1[8];
#pragma unroll
            for (int nt = 0; nt < 8; nt++) {
                const float* vp = &Vs[(wn2 * 64 + nt * 8 + gid) * 64];
                vb0[nt] = fb(vp[cl]); vb1[nt] = fb(vp[ch]);
            }
#pragma unroll
            for (int nt = 0; nt < 8; nt++)
#pragma unroll
                for (int mt = 0; mt < 2; mt++)
                    mma_tf32(oa[mt][nt], pa[mt][0], pa[mt][1], pa[mt][2], pa[mt][3],
                             vb0[nt], vb1[nt]);
        }
    }

    // final row-sum reduction across the quad, then across the two j-halves
    lp0 += __shfl_xor_sync(0xffffffffu, lp0, 1);
    lp0 += __shfl_xor_sync(0xffffffffu, lp0, 2);
    lp1 += __shfl_xor_sync(0xffffffffu, lp1, 1);
    lp1 += __shfl_xor_sync(0xffffffffu, lp1, 2);
    if (tig == 0) { reds[r0 * 2 + wn1] = lp0; reds[r1 * 2 + wn1] = lp1; }
    __syncthreads();

    // epilogue: O/l + residual, round, store X'[i][c]
    float* Xb = X + ((size_t)b * NHW + i0) * NCQ;
    const float* qres = queryT + ((size_t)b * NHW + i0) * NCQ;
#pragma unroll
    for (int mt = 0; mt < 2; mt++) {
        int rr0 = wm2 * 32 + mt * 16 + gid, rr1 = rr0 + 8;
        float inv0 = 1.f / (reds[rr0 * 2] + reds[rr0 * 2 + 1]);
        float inv1 = 1.f / (reds[rr1 * 2] + reds[rr1 * 2 + 1]);
#pragma unroll
        for (int nt = 0; nt < 8; nt++) {
            int col = wn2 * 64 + nt * 8 + tig * 2;
            float2 q0 = *(const float2*)&qres[(size_t)rr0 * NCQ + col];
            float2 q1 = *(const float2*)&qres[(size_t)rr1 * NCQ + col];
            float2 o0, o1;
            o0.x = rna(oa[mt][nt][0] * inv0 + q0.x);
            o0.y = rna(oa[mt][nt][1] * inv0 + q0.y);
            o1.x = rna(oa[mt][nt][2] * inv1 + q1.x);
            o1.y = rna(oa[mt][nt][3] * inv1 + q1.y);
            *(float2*)&Xb[(size_t)rr0 * NCQ + col] = o0;
            *(float2*)&Xb[(size_t)rr1 * NCQ + col] = o1;
        }
    }
}

// ---------------- normalize + affine -> out (float4) -----------------------------
__global__ void norm_kernel(const float* __restrict__ gamma, const float* __restrict__ beta,
                            float* __restrict__ out) {
    int idx = (blockIdx.x * blockDim.x + threadIdx.x) * 4;
    int b = idx >> 18;
    int o = (idx >> 10) & 255;
    float s = g_sums[b * 2], s2 = g_sums[b * 2 + 1];
    const float n = (float)GN_N;
    float mu = s / n;
    float var = s2 / n - mu * mu;
    float rstd = rsqrtf(var + 1e-5f);
    float ga = gamma[o] * rstd, be = beta[o] - mu * ga;
    float4 f = *(const float4*)&g_F[idx];
    float4 r;
    r.x = f.x * ga + be; r.y = f.y * ga + be;
    r.z = f.z * ga + be; r.w = f.w * ga + be;
    *(float4*)&out[idx] = r;
}

// ---------------- launch -----------------------------------------------------------
extern "C" void kernel_launch(void* const* d_in, const int* in_sizes, int n_in,
                              void* d_out, int out_size) {
    const float* query = (const float*)d_in[0];
    const float* ctx   = (const float*)d_in[1];
    const float* Wq = (const float*)d_in[2];  const float* bq = (const float*)d_in[3];
    const float* Wk = (const float*)d_in[4];  const float* bk = (const float*)d_in[5];
    const float* Wv = (const float*)d_in[6];  const float* bv = (const float*)d_in[7];
    const float* Wp = (const float*)d_in[8];  const float* bp = (const float*)d_in[9];
    const float* gamma = (const float*)d_in[10];
    const float* beta  = (const float*)d_in[11];
    float* out = (float*)d_out;

    float *p_qT, *p_kT, *p_v, *p_X, *p_F, *p_queryT, *p_Wq, *p_Wp;
    cudaGetSymbolAddress((void**)&p_qT, g_qT);
    cudaGetSymbolAddress((void**)&p_kT, g_kT);
    cudaGetSymbolAddress((void**)&p_v, g_v);
    cudaGetSymbolAddress((void**)&p_X, g_X);
    cudaGetSymbolAddress((void**)&p_F, g_F);
    cudaGetSymbolAddress((void**)&p_queryT, g_queryT);
    cudaGetSymbolAddress((void**)&p_Wq, g_Wq);
    cudaGetSymbolAddress((void**)&p_Wp, g_Wp);

    static int smem_set = 0;
    if (!smem_set) {
        cudaFuncSetAttribute(flash_kernel, cudaFuncAttributeMaxDynamicSharedMemorySize,
                             F_SMEM_FLOATS * (int)sizeof(float));
        smem_set = 1;
    }

    // preprocessing
    prep_weights<<<256, 256>>>(Wq, Wp);
    proj_kernel<<<dim3(NHW / 64, NB), 256>>>(ctx, Wk, bk, Wv, bv);
    transpose_round<<<dim3(NHW / 32, NCQ / 32, NB), dim3(32, 32)>>>(query);

    // q projection: qT[i][c'] = queryT[i][c] x Wq[c'][c] + bq
    gemm_tc<<<dim3(NINTER / 128, NHW / 128, NB), 256>>>(
        p_queryT, p_Wq, p_qT,
        (size_t)NHW * NCQ, 0, (size_t)NHW * NINTER,
        nullptr, bq, NHW, NINTER, NCQ, 1, 0);

    // flash attention -> X'[b][i][c] (with residual, rounded)
    flash_kernel<<<dim3(NHW / 128, NB), 512, F_SMEM_FLOATS * sizeof(float)>>>(
        p_qT, p_kT, p_v, p_queryT, p_X);

    // fused conv: F[o][i] = Wp[o][:] . X'[i][:] + bp[o]   (+ GN stats)
    gemm_tc<<<dim3(NHW / 128, NCQ / 128, NB), 256>>>(
        p_Wp, p_X, p_F,
        0, (size_t)NHW * NCQ, (size_t)NCQ * NHW,
        bp, nullptr, NCQ, NHW, NCQ, 0, 1);

    // group norm apply
    norm_kernel<<<(NB * NCQ * NHW) / 1024, 256>>>(gamma, beta, out);
}

// round 6
// speedup vs baseline: 4.5281x; 1.4337x over previous
#include <cuda_runtime.h>
#include <cuda_fp16.h>
#include <math.h>
#include <stdint.h>

#define NB 32
#define NCQ 256
#define NCC 3
#define NINTER 128
#define NHW 1024
#define NHC 224
#define GN_N (NCQ*NHW)

// ---------------- scratch (static device memory, no allocs) ----------------
__device__ __half g_qT[NB*NHW*NINTER];              // [b][i][c']
__device__ __half g_kT[NB*NHW*NINTER];              // [b][j][c']
__device__ __half g_v [NB*NCQ*NHW];                 // [b][c][j]
__device__ __half g_X [NB*NHW*NCQ];                 // X'[b][i][c]
__device__ float  g_F [NB*NCQ*NHW];                 // fused F[b][o][i] (fp32)
__device__ __half g_queryT[NB*NHW*NCQ];             // [b][i][c]
__device__ __half g_Wq[NINTER*NCQ];
__device__ __half g_Wp[NCQ*NCQ];
__device__ float  g_sums[NB*2];

__device__ __forceinline__ uint32_t pk2(float a, float b) {
    __half2 h = __floats2half2_rn(a, b);
    return *(uint32_t*)&h;
}
__device__ __forceinline__ float2 up2(uint32_t u) {
    __half2 h = *(__half2*)&u;
    return __half22float2(h);
}

__device__ __forceinline__ void mma_f16(float* d, uint32_t a0, uint32_t a1, uint32_t a2,
                                        uint32_t a3, uint32_t b0, uint32_t b1) {
    asm volatile(
        "mma.sync.aligned.m16n8k16.row.col.f32.f16.f16.f32 "
        "{%0,%1,%2,%3}, {%4,%5,%6,%7}, {%8,%9}, {%0,%1,%2,%3};"
        : "+f"(d[0]), "+f"(d[1]), "+f"(d[2]), "+f"(d[3])
        : "r"(a0), "r"(a1), "r"(a2), "r"(a3), "r"(b0), "r"(b1));
}

__device__ __forceinline__ void cpa16(void* dst, const void* src) {
    uint32_t d = (uint32_t)__cvta_generic_to_shared(dst);
    asm volatile("cp.async.cg.shared.global [%0], [%1], 16;" :: "r"(d), "l"(src));
}
#define CP_COMMIT asm volatile("cp.async.commit_group;")

// ---------------- fused resize + k/v projection (fp16 out) ----------------------
__global__ __launch_bounds__(256)
void proj_kernel(const float* __restrict__ ctx,
                 const float* __restrict__ Wk, const float* __restrict__ bk,
                 const float* __restrict__ Wv, const float* __restrict__ bv) {
    __shared__ float sctx[NCC][64];
    __shared__ float sWk[NINTER*3], sbk[NINTER];
    __shared__ float sWv[NCQ*3], sbv[NCQ];
    int tid = threadIdx.x;
    int b = blockIdx.y, j0 = blockIdx.x * 64;

    for (int i = tid; i < NINTER*3; i += 256) sWk[i] = Wk[i];
    for (int i = tid; i < NCQ*3; i += 256)    sWv[i] = Wv[i];
    if (tid < NINTER) sbk[tid] = bk[tid];
    if (tid < NCQ)    sbv[tid] = bv[tid];

    if (tid < NCC * 64) {
        int c = tid >> 6, jj = tid & 63;
        int p = j0 + jj;
        int y = p >> 5, x = p & 31;
        float sy = 7.f * y + 3.f;
        float sx = 7.f * x + 3.f;
        int y0 = (int)floorf(sy), x0 = (int)floorf(sx);
        float fy = sy - y0, fx = sx - x0;
        int y1 = min(y0 + 1, NHC - 1), x1 = min(x0 + 1, NHC - 1);
        y0 = max(y0, 0); x0 = max(x0, 0);
        const float* base = ctx + ((size_t)b * NCC + c) * NHC * NHC;
        float v00 = base[y0 * NHC + x0], v01 = base[y0 * NHC + x1];
        float v10 = base[y1 * NHC + x0], v11 = base[y1 * NHC + x1];
        sctx[c][jj] = (1.f - fy) * ((1.f - fx) * v00 + fx * v01)
                    + fy * ((1.f - fx) * v10 + fx * v11);
    }
    __syncthreads();

    __half* kout = g_kT + ((size_t)b * NHW + j0) * NINTER;
#pragma unroll 4
    for (int o = tid; o < 64 * NINTER; o += 256) {
        int jj = o >> 7, c = o & 127;
        kout[(size_t)jj * NINTER + c] = __float2half_rn(
            sbk[c] + sWk[c*3]*sctx[0][jj] + sWk[c*3+1]*sctx[1][jj] + sWk[c*3+2]*sctx[2][jj]);
    }
    __half* vout = g_v + (size_t)b * NCQ * NHW + j0;
#pragma unroll 4
    for (int o = tid; o < NCQ * 64; o += 256) {
        int c = o >> 6, jj = o & 63;
        vout[(size_t)c * NHW + jj] = __float2half_rn(
            sbv[c] + sWv[c*3]*sctx[0][jj] + sWv[c*3+1]*sctx[1][jj] + sWv[c*3+2]*sctx[2][jj]);
    }
}

// ---------------- queryT transpose + half ----------------------------------------
__global__ void transpose_round(const float* __restrict__ in) {
    __shared__ float t[32][33];
    int b = blockIdx.z;
    int i0 = blockIdx.x * 32, c0 = blockIdx.y * 32;
    const float* ip = in + (size_t)b * NCQ * NHW;
    __half* op = g_queryT + (size_t)b * NHW * NCQ;
    t[threadIdx.y][threadIdx.x] = ip[(size_t)(c0 + threadIdx.y) * NHW + i0 + threadIdx.x];
    __syncthreads();
    op[(size_t)(i0 + threadIdx.y) * NCQ + c0 + threadIdx.x] =
        __float2half_rn(t[threadIdx.x][threadIdx.y]);
}

// ---------------- weight rounding + stats zero -------------------------------------
__global__ void prep_weights(const float* __restrict__ Wq, const float* __restrict__ Wp) {
    int i = blockIdx.x * blockDim.x + threadIdx.x;
    if (i < NINTER * NCQ) g_Wq[i] = __float2half_rn(Wq[i]);
    if (i < NCQ * NCQ)    g_Wp[i] = __float2half_rn(Wp[i]);
    if (i < NB * 2)       g_sums[i] = 0.f;
}

// ---------------- fp16 tensor-core ABT GEMM ----------------------------------------
// C[b][m][n] = sum_k A[b][m][k]*B[b][n][k] (+bias_m/+bias_n). K mult of 32.
// BM=BN=128, BK=32 halves. 256 thr, warp grid 2x4, warp tile 64x32.
#define HP 20   // smem row pitch in u32 (16 + 4 pad)
__global__ __launch_bounds__(256, 2)
void hgemm(const __half* __restrict__ A, const __half* __restrict__ B, void* __restrict__ Cv,
           size_t sA, size_t sB, size_t sC,
           const float* __restrict__ bias_m, const float* __restrict__ bias_n,
           int M, int N, int K, int outHalf, int doStats) {
    __shared__ uint32_t As[2][128 * HP];
    __shared__ uint32_t Bs[2][128 * HP];
    __shared__ float rs[8], rq[8];
    int b = blockIdx.z;
    A += (size_t)b * sA; B += (size_t)b * sB;
    int m0 = blockIdx.y * 128, n0 = blockIdx.x * 128;
    int tid = threadIdx.x, lane = tid & 31, wid = tid >> 5;
    int wm = wid >> 2, wn = wid & 3;
    int gid = lane >> 2, tig = lane & 3;

    float acc[4][4][4];
#pragma unroll
    for (int i = 0; i < 4; i++)
#pragma unroll
        for (int j = 0; j < 4; j++)
#pragma unroll
            for (int r = 0; r < 4; r++) acc[i][j][r] = 0.f;

    // loads: tile = 128 rows x 32 halves = 128x4 segs of 16B; 512 segs / 256 thr = 2
    int seg0 = tid, seg1 = tid + 256;
    int lr0 = seg0 >> 2, ls0 = (seg0 & 3) * 8;    // half offset in row
    int lr1 = seg1 >> 2, ls1 = (seg1 & 3) * 8;
    int nk = K / 32;
    uint4 ra0, ra1, rb0, rb1;

    ra0 = *(const uint4*)&A[(size_t)(m0 + lr0) * K + ls0];
    ra1 = *(const uint4*)&A[(size_t)(m0 + lr1) * K + ls1];
    rb0 = *(const uint4*)&B[(size_t)(n0 + lr0) * K + ls0];
    rb1 = *(const uint4*)&B[(size_t)(n0 + lr1) * K + ls1];
    {
        uint32_t* a = &As[0][lr0 * HP + (ls0 >> 1)];
        a[0] = ra0.x; a[1] = ra0.y; a[2] = ra0.z; a[3] = ra0.w;
        a = &As[0][lr1 * HP + (ls1 >> 1)];
        a[0] = ra1.x; a[1] = ra1.y; a[2] = ra1.z; a[3] = ra1.w;
        uint32_t* p = &Bs[0][lr0 * HP + (ls0 >> 1)];
        p[0] = rb0.x; p[1] = rb0.y; p[2] = rb0.z; p[3] = rb0.w;
        p = &Bs[0][lr1 * HP + (ls1 >> 1)];
        p[0] = rb1.x; p[1] = rb1.y; p[2] = rb1.z; p[3] = rb1.w;
    }
    __syncthreads();

    for (int kt = 0; kt < nk; kt++) {
        int cur = kt & 1;
        if (kt + 1 < nk) {
            int kb = (kt + 1) * 32;
            ra0 = *(const uint4*)&A[(size_t)(m0 + lr0) * K + kb + ls0];
            ra1 = *(const uint4*)&A[(size_t)(m0 + lr1) * K + kb + ls1];
            rb0 = *(const uint4*)&B[(size_t)(n0 + lr0) * K + kb + ls0];
            rb1 = *(const uint4*)&B[(size_t)(n0 + lr1) * K + kb + ls1];
        }
#pragma unroll
        for (int ks = 0; ks < 2; ks++) {
            int k0 = ks * 8;   // u32 units (16 halves)
            uint32_t afr[4][4], bfr[4][2];
#pragma unroll
            for (int mt = 0; mt < 4; mt++) {
                const uint32_t* ap = &As[cur][(wm * 64 + mt * 16 + gid) * HP + k0 + tig];
                afr[mt][0] = ap[0];
                afr[mt][1] = ap[8 * HP];
                afr[mt][2] = ap[4];
                afr[mt][3] = ap[8 * HP + 4];
            }
#pragma unroll
            for (int nt = 0; nt < 4; nt++) {
                const uint32_t* bp = &Bs[cur][(wn * 32 + nt * 8 + gid) * HP + k0 + tig];
                bfr[nt][0] = bp[0];
                bfr[nt][1] = bp[4];
            }
#pragma unroll
            for (int mt = 0; mt < 4; mt++)
#pragma unroll
                for (int nt = 0; nt < 4; nt++)
                    mma_f16(acc[mt][nt], afr[mt][0], afr[mt][1], afr[mt][2], afr[mt][3],
                            bfr[nt][0], bfr[nt][1]);
        }
        if (kt + 1 < nk) {
            int nxt = cur ^ 1;
            uint32_t* a = &As[nxt][lr0 * HP + (ls0 >> 1)];
            a[0] = ra0.x; a[1] = ra0.y; a[2] = ra0.z; a[3] = ra0.w;
            a = &As[nxt][lr1 * HP + (ls1 >> 1)];
            a[0] = ra1.x; a[1] = ra1.y; a[2] = ra1.z; a[3] = ra1.w;
            uint32_t* p = &Bs[nxt][lr0 * HP + (ls0 >> 1)];
            p[0] = rb0.x; p[1] = rb0.y; p[2] = rb0.z; p[3] = rb0.w;
            p = &Bs[nxt][lr1 * HP + (ls1 >> 1)];
            p[0] = rb1.x; p[1] = rb1.y; p[2] = rb1.z; p[3] = rb1.w;
        }
        __syncthreads();
    }

    float ls = 0.f, lq = 0.f;
#pragma unroll
    for (int mt = 0; mt < 4; mt++) {
#pragma unroll
        for (int nt = 0; nt < 4; nt++) {
            int row0 = m0 + wm * 64 + mt * 16 + gid;
            int col  = n0 + wn * 32 + nt * 8 + tig * 2;
#pragma unroll
            for (int h = 0; h < 2; h++) {
                int row = row0 + h * 8;
                float x = acc[mt][nt][h * 2], y = acc[mt][nt][h * 2 + 1];
                if (bias_m) { float bm = bias_m[row]; x += bm; y += bm; }
                if (bias_n) { x += bias_n[col]; y += bias_n[col + 1]; }
                if (doStats) { ls += x + y; lq += x * x + y * y; }
                if (outHalf) {
                    uint32_t* C = (uint32_t*)Cv + ((size_t)b * sC + (size_t)row * N + col) / 2;
                    *C = pk2(x, y);
                } else {
                    float* C = (float*)Cv + (size_t)b * sC + (size_t)row * N + col;
                    float2 r; r.x = x; r.y = y;
                    *(float2*)C = r;
                }
            }
        }
    }
    if (doStats) {
#pragma unroll
        for (int o = 16; o; o >>= 1) {
            ls += __shfl_xor_sync(0xffffffffu, ls, o);
            lq += __shfl_xor_sync(0xffffffffu, lq, o);
        }
        if (lane == 0) { rs[wid] = ls; rq[wid] = lq; }
        __syncthreads();
        if (tid == 0) {
            float ts = 0.f, tq = 0.f;
#pragma unroll
            for (int i = 0; i < 8; i++) { ts += rs[i]; tq += rq[i]; }
            atomicAdd(&g_sums[b * 2], ts);
            atomicAdd(&g_sums[b * 2 + 1], tq);
        }
    }
}

// ---------------- flash attention fp16: flash-2 online softmax ---------------------
// IT=128, JT=64, 512 threads. Q/K/V/P fp16 in smem (u32 granules, XOR swizzle).
// smem u32 layout: Qs 128x64, Ks 2x64x64, Vs 256x32, Ps 128x32; floats: redm 128x2,
// m_s 128, lred 128x2.
#define F_SMEM_BYTES ((128*64 + 2*64*64 + 256*32 + 128*32) * 4 + (128*2 + 128 + 128*2) * 4)

__global__ __launch_bounds__(512, 1)
void flash_kernel(const __half* __restrict__ qT, const __half* __restrict__ kT,
                  const __half* __restrict__ v, const __half* __restrict__ queryT,
                  __half* __restrict__ X) {
    extern __shared__ uint32_t smu[];
    uint32_t* Qs = smu;                    // 128 x 64
    uint32_t* Ks = Qs + 128 * 64;          // 2 x 64 x 64
    uint32_t* Vs = Ks + 2 * 64 * 64;       // 256 x 32
    uint32_t* Ps = Vs + 256 * 32;          // 128 x 32
    float* redm = (float*)(Ps + 128 * 32); // 128 x 2
    float* m_s  = redm + 128 * 2;          // 128
    float* lred = m_s + 128;               // 128 x 2

    int b = blockIdx.y, i0 = blockIdx.x * 128;
    const __half* qTb = qT + ((size_t)b * NHW + i0) * NINTER;
    const __half* kTb = kT + (size_t)b * NHW * NINTER;
    const __half* vb  = v  + (size_t)b * NCQ * NHW;

    int tid = threadIdx.x, lane = tid & 31, w = tid >> 5;
    int gid = lane >> 2, tig = lane & 3;
    int wm1 = w >> 1, wn1 = w & 1;         // gemm1: 8(m) x 2(n), warp tile 16x32
    int wm2 = w >> 2, wn2 = w & 3;         // gemm2: 4(m) x 4(n), warp tile 32x64
    int qm = gid << 2;

    // load Q tile 128x128 halves (swizzled u32x4 stores): 2048 segs / 512 = 4
#pragma unroll
    for (int it = 0; it < 4; it++) {
        int id = tid + it * 512;
        int r = id >> 4, c4 = (id & 15) << 2;      // u32 col
        uint4 vq = *(const uint4*)&qTb[(size_t)r * NINTER + c4 * 2];
        *(uint4*)&Qs[r * 64 + (c4 ^ ((r & 7) << 2))] = vq;
    }
    if (tid < 128) m_s[tid] = -1e30f;

    // prologue: prefetch K0, V0
#pragma unroll
    for (int it = 0; it < 2; it++) {
        int id = tid + it * 512;
        int r = id >> 4, c4 = (id & 15) << 2;
        cpa16(&Ks[r * 64 + (c4 ^ ((r & 7) << 2))], &kTb[(size_t)r * NINTER + c4 * 2]);
    }
    CP_COMMIT;
#pragma unroll
    for (int it = 0; it < 4; it++) {
        int id = tid + it * 512;
        int r = id >> 3, c4 = (id & 7) << 2;
        cpa16(&Vs[r * 32 + (c4 ^ ((r & 7) << 2))], &vb[(size_t)r * NHW + c4 * 2]);
    }
    CP_COMMIT;

    float oa[2][8][4];
#pragma unroll
    for (int mt = 0; mt < 2; mt++)
#pragma unroll
        for (int nt = 0; nt < 8; nt++)
#pragma unroll
            for (int r = 0; r < 4; r++) oa[mt][nt][r] = 0.f;
    float lp0 = 0.f, lp1 = 0.f;
    int r0 = wm1 * 16 + gid, r1 = r0 + 8;

    for (int t = 0; t < 16; t++) {
        int buf = t & 1;
        __syncthreads();        // (top) gemm2(t-1) done; Qs/m_s ready at t=0
        if (t > 0) {            // prefetch V(t)
            int j0 = t * 64;
#pragma unroll
            for (int it = 0; it < 4; it++) {
                int id = tid + it * 512;
                int r = id >> 3, c4 = (id & 7) << 2;
                cpa16(&Vs[r * 32 + (c4 ^ ((r & 7) << 2))], &vb[(size_t)r * NHW + j0 + c4 * 2]);
            }
            CP_COMMIT;
        }
        if (t < 15) {           // prefetch K(t+1)
            int j0 = (t + 1) * 64;
            uint32_t* kd = &Ks[(buf ^ 1) * 64 * 64];
#pragma unroll
            for (int it = 0; it < 2; it++) {
                int id = tid + it * 512;
                int r = id >> 4, c4 = (id & 15) << 2;
                cpa16(&kd[r * 64 + (c4 ^ ((r & 7) << 2))], &kTb[(size_t)(j0 + r) * NINTER + c4 * 2]);
            }
            CP_COMMIT;
        }
        if (t == 15) { asm volatile("cp.async.wait_group 1;"); }
        else         { asm volatile("cp.async.wait_group 2;"); }
        __syncthreads();        // (K-vis)

        // ---- gemm1: S(16x32 per warp) = Q x K^T, fp16 k16 steps ----
        float s[4][4];
#pragma unroll
        for (int nt = 0; nt < 4; nt++)
#pragma unroll
            for (int r = 0; r < 4; r++) s[nt][r] = 0.f;
        {
            const uint32_t* qp = &Qs[r0 * 64];
            const uint32_t* kp = &Ks[buf * 64 * 64 + (wn1 * 32 + gid) * 64];
#pragma unroll
            for (int k = 0; k < 8; k++) {
                int cl = (k * 8 + tig) ^ qm, ch = (k * 8 + 4 + tig) ^ qm;
                uint32_t a0 = qp[cl], a1 = qp[8 * 64 + cl];
                uint32_t a2 = qp[ch], a3 = qp[8 * 64 + ch];
                uint32_t b0[4], b1[4];
#pragma unroll
                for (int nt = 0; nt < 4; nt++) {
                    b0[nt] = kp[nt * 8 * 64 + cl];
                    b1[nt] = kp[nt * 8 * 64 + ch];
                }
#pragma unroll
                for (int nt = 0; nt < 4; nt++)
                    mma_f16(s[nt], a0, a1, a2, a3, b0[nt], b1[nt]);
            }
        }

        // ---- tile row max (quad shuffle), publish to redm ----
        float mx0 = -1e30f, mx1 = -1e30f;
#pragma unroll
        for (int nt = 0; nt < 4; nt++) {
            mx0 = fmaxf(mx0, fmaxf(s[nt][0], s[nt][1]));
            mx1 = fmaxf(mx1, fmaxf(s[nt][2], s[nt][3]));
        }
        mx0 = fmaxf(mx0, __shfl_xor_sync(0xffffffffu, mx0, 1));
        mx0 = fmaxf(mx0, __shfl_xor_sync(0xffffffffu, mx0, 2));
        mx1 = fmaxf(mx1, __shfl_xor_sync(0xffffffffu, mx1, 1));
        mx1 = fmaxf(mx1, __shfl_xor_sync(0xffffffffu, mx1, 2));
        if (tig == 0) { redm[r0 * 2 + wn1] = mx0; redm[r1 * 2 + wn1] = mx1; }
        __syncthreads();        // (A) redm visible; m_s still old

        // ---- P = exp(s - mnew) fp16, l update (per-lane partials) ----
        float m_old0 = m_s[r0], m_old1 = m_s[r1];
        float mn0 = fmaxf(m_old0, fmaxf(redm[r0 * 2], redm[r0 * 2 + 1]));
        float mn1 = fmaxf(m_old1, fmaxf(redm[r1 * 2], redm[r1 * 2 + 1]));
        float al0 = __expf(m_old0 - mn0), al1 = __expf(m_old1 - mn1);
        float s0 = 0.f, s1 = 0.f;
#pragma unroll
        for (int nt = 0; nt < 4; nt++) {
            float e0 = __expf(s[nt][0] - mn0);
            float e1 = __expf(s[nt][1] - mn0);
            float e2 = __expf(s[nt][2] - mn1);
            float e3 = __expf(s[nt][3] - mn1);
            s0 += e0 + e1; s1 += e2 + e3;
            int col = (wn1 * 16 + nt * 4 + tig) ^ qm;     // u32 col
            Ps[r0 * 32 + col] = pk2(e0, e1);
            Ps[r1 * 32 + col] = pk2(e2, e3);
        }
        lp0 = lp0 * al0 + s0;
        lp1 = lp1 * al1 + s1;

        // ---- O rescale (gemm2 rows; m_s still old) ----
        float alo[2][2];
#pragma unroll
        for (int mt = 0; mt < 2; mt++) {
            int rr0 = wm2 * 32 + mt * 16 + gid, rr1 = rr0 + 8;
            float mo = m_s[rr0];
            alo[mt][0] = __expf(mo - fmaxf(mo, fmaxf(redm[rr0 * 2], redm[rr0 * 2 + 1])));
            mo = m_s[rr1];
            alo[mt][1] = __expf(mo - fmaxf(mo, fmaxf(redm[rr1 * 2], redm[rr1 * 2 + 1])));
        }
#pragma unroll
        for (int mt = 0; mt < 2; mt++)
#pragma unroll
            for (int nt = 0; nt < 8; nt++) {
                oa[mt][nt][0] *= alo[mt][0]; oa[mt][nt][1] *= alo[mt][0];
                oa[mt][nt][2] *= alo[mt][1]; oa[mt][nt][3] *= alo[mt][1];
            }

        if (t == 15) { asm volatile("cp.async.wait_group 0;"); }
        else         { asm volatile("cp.async.wait_group 1;"); }
        __syncthreads();        // (B) Ps + V(t) visible; m_s readers done

        if (wn1 == 0 && tig == 0) { m_s[r0] = mn0; m_s[r1] = mn1; }

        // ---- gemm2: O(32x64 per warp) += P x V, 4 fp16 k16 steps ----
#pragma unroll
        for (int k = 0; k < 4; k++) {
            int cl = (k * 8 + tig) ^ qm, ch = (k * 8 + 4 + tig) ^ qm;
            uint32_t pa[2][4];
#pragma unroll
            for (int mt = 0; mt < 2; mt++) {
                const uint32_t* pp = &Ps[(wm2 * 32 + mt * 16 + gid) * 32];
                pa[mt][0] = pp[cl];
                pa[mt][1] = pp[8 * 32 + cl];
                pa[mt][2] = pp[ch];
                pa[mt][3] = pp[8 * 32 + ch];
            }
            uint32_t vb0[8], vb1[8];
#pragma unroll
            for (int nt = 0; nt < 8; nt++) {
                const uint32_t* vp = &Vs[(wn2 * 64 + nt * 8 + gid) * 32];
                vb0[nt] = vp[cl]; vb1[nt] = vp[ch];
            }
#pragma unroll
            for (int nt = 0; nt < 8; nt++)
#pragma unroll
                for (int mt = 0; mt < 2; mt++)
                    mma_f16(oa[mt][nt], pa[mt][0], pa[mt][1], pa[mt][2], pa[mt][3],
                            vb0[nt], vb1[nt]);
        }
    }

    // final l: quad reduce, combine halves via smem
    lp0 += __shfl_xor_sync(0xffffffffu, lp0, 1);
    lp0 += __shfl_xor_sync(0xffffffffu, lp0, 2);
    lp1 += __shfl_xor_sync(0xffffffffu, lp1, 1);
    lp1 += __shfl_xor_sync(0xffffffffu, lp1, 2);
    if (tig == 0) { lred[r0 * 2 + wn1] = lp0; lred[r1 * 2 + wn1] = lp1; }
    __syncthreads();

    // epilogue: O/l + residual -> half X'
    uint32_t* Xb = (uint32_t*)(X + ((size_t)b * NHW + i0) * NCQ);
    const uint32_t* qres = (const uint32_t*)(queryT + ((size_t)b * NHW + i0) * NCQ);
#pragma unroll
    for (int mt = 0; mt < 2; mt++) {
        int rr0 = wm2 * 32 + mt * 16 + gid, rr1 = rr0 + 8;
        float inv0 = 1.f / (lred[rr0 * 2] + lred[rr0 * 2 + 1]);
        float inv1 = 1.f / (lred[rr1 * 2] + lred[rr1 * 2 + 1]);
#pragma unroll
        for (int nt = 0; nt < 8; nt++) {
            int cu = wn2 * 32 + nt * 4 + tig;             // u32 col
            float2 q0 = up2(qres[rr0 * 128 + cu]);
            float2 q1 = up2(qres[rr1 * 128 + cu]);
            Xb[rr0 * 128 + cu] = pk2(oa[mt][nt][0] * inv0 + q0.x,
                                     oa[mt][nt][1] * inv0 + q0.y);
            Xb[rr1 * 128 + cu] = pk2(oa[mt][nt][2] * inv1 + q1.x,
                                     oa[mt][nt][3] * inv1 + q1.y);
        }
    }
}

// ---------------- normalize + affine -> out (float4) --------------------------------
__global__ void norm_kernel(const float* __restrict__ gamma, const float* __restrict__ beta,
                            float* __restrict__ out) {
    int idx = (blockIdx.x * blockDim.x + threadIdx.x) * 4;
    int b = idx >> 18;
    int o = (idx >> 10) & 255;
    float s = g_sums[b * 2], s2 = g_sums[b * 2 + 1];
    const float n = (float)GN_N;
    float mu = s / n;
    float var = s2 / n - mu * mu;
    float rstd = rsqrtf(var + 1e-5f);
    float ga = gamma[o] * rstd, be = beta[o] - mu * ga;
    float4 f = *(const float4*)&g_F[idx];
    float4 r;
    r.x = f.x * ga + be; r.y = f.y * ga + be;
    r.z = f.z * ga + be; r.w = f.w * ga + be;
    *(float4*)&out[idx] = r;
}

// ---------------- launch --------------------------------------------------------------
extern "C" void kernel_launch(void* const* d_in, const int* in_sizes, int n_in,
                              void* d_out, int out_size) {
    const float* query = (const float*)d_in[0];
    const float* ctx   = (const float*)d_in[1];
    const float* Wq = (const float*)d_in[2];  const float* bq = (const float*)d_in[3];
    const float* Wk = (const float*)d_in[4];  const float* bk = (const float*)d_in[5];
    const float* Wv = (const float*)d_in[6];  const float* bv = (const float*)d_in[7];
    const float* Wp = (const float*)d_in[8];  const float* bp = (const float*)d_in[9];
    const float* gamma = (const float*)d_in[10];
    const float* beta  = (const float*)d_in[11];
    float* out = (float*)d_out;

    __half *p_qT, *p_kT, *p_v, *p_X, *p_queryT, *p_Wq, *p_Wp;
    float *p_F;
    cudaGetSymbolAddress((void**)&p_qT, g_qT);
    cudaGetSymbolAddress((void**)&p_kT, g_kT);
    cudaGetSymbolAddress((void**)&p_v, g_v);
    cudaGetSymbolAddress((void**)&p_X, g_X);
    cudaGetSymbolAddress((void**)&p_F, g_F);
    cudaGetSymbolAddress((void**)&p_queryT, g_queryT);
    cudaGetSymbolAddress((void**)&p_Wq, g_Wq);
    cudaGetSymbolAddress((void**)&p_Wp, g_Wp);

    static int smem_set = 0;
    if (!smem_set) {
        cudaFuncSetAttribute(flash_kernel, cudaFuncAttributeMaxDynamicSharedMemorySize,
                             F_SMEM_BYTES);
        smem_set = 1;
    }

    // preprocessing
    prep_weights<<<256, 256>>>(Wq, Wp);
    proj_kernel<<<dim3(NHW / 64, NB), 256>>>(ctx, Wk, bk, Wv, bv);
    transpose_round<<<dim3(NHW / 32, NCQ / 32, NB), dim3(32, 32)>>>(query);

    // q projection: qT[i][c'] = queryT[i][:] . Wq[c'][:] + bq  -> half
    hgemm<<<dim3(NINTER / 128, NHW / 128, NB), 256>>>(
        p_queryT, p_Wq, p_qT,
        (size_t)NHW * NCQ, 0, (size_t)NHW * NINTER,
        nullptr, bq, NHW, NINTER, NCQ, 1, 0);

    // flash attention -> X'[b][i][c] half (with residual)
    flash_kernel<<<dim3(NHW / 128, NB), 512, F_SMEM_BYTES>>>(
        p_qT, p_kT, p_v, p_queryT, p_X);

    // fused conv: F[o][i] = Wp[o][:] . X'[i][:] + bp[o]  -> fp32 (+ GN stats)
    hgemm<<<dim3(NHW / 128, NCQ / 128, NB), 256>>>(
        p_Wp, p_X, p_F,
        0, (size_t)NHW * NCQ, (size_t)NCQ * NHW,
        bp, nullptr, NCQ, NHW, NCQ, 0, 1);

    // group norm apply
    norm_kernel<<<(NB * NCQ * NHW) / 1024, 256>>>(gamma, beta, out);
}

// round 7
// speedup vs baseline: 4.6452x; 1.0259x over previous
#include <cuda_runtime.h>
#include <cuda_fp16.h>
#include <math.h>
#include <stdint.h>

#define NB 32
#define NCQ 256
#define NCC 3
#define NINTER 128
#define NHW 1024
#define NHC 224
#define GN_N (NCQ*NHW)

// ---------------- scratch (static device memory, no allocs) ----------------
__device__ __half g_qT[NB*NHW*NINTER];              // [b][i][c']
__device__ __half g_kT[NB*NHW*NINTER];              // [b][j][c']
__device__ __half g_v [NB*NCQ*NHW];                 // [b][c][j]
__device__ __half g_X [NB*NHW*NCQ];                 // X'[b][i][c]
__device__ float  g_F [NB*NCQ*NHW];                 // fused F[b][o][i] (fp32)
__device__ __half g_queryT[NB*NHW*NCQ];             // [b][i][c]
__device__ __half g_Wq[NINTER*NCQ];
__device__ __half g_Wp[NCQ*NCQ];
__device__ float  g_sums[NB*2];

__device__ __forceinline__ uint32_t pk2(float a, float b) {
    __half2 h = __floats2half2_rn(a, b);
    return *(uint32_t*)&h;
}
__device__ __forceinline__ float2 up2(uint32_t u) {
    __half2 h = *(__half2*)&u;
    return __half22float2(h);
}

__device__ __forceinline__ void mma_f16(float* d, uint32_t a0, uint32_t a1, uint32_t a2,
                                        uint32_t a3, uint32_t b0, uint32_t b1) {
    asm volatile(
        "mma.sync.aligned.m16n8k16.row.col.f32.f16.f16.f32 "
        "{%0,%1,%2,%3}, {%4,%5,%6,%7}, {%8,%9}, {%0,%1,%2,%3};"
        : "+f"(d[0]), "+f"(d[1]), "+f"(d[2]), "+f"(d[3])
        : "r"(a0), "r"(a1), "r"(a2), "r"(a3), "r"(b0), "r"(b1));
}

__device__ __forceinline__ void ldsm4(uint32_t& r0, uint32_t& r1, uint32_t& r2, uint32_t& r3,
                                      uint32_t adr) {
    asm volatile("ldmatrix.sync.aligned.m8n8.x4.shared.b16 {%0,%1,%2,%3}, [%4];"
                 : "=r"(r0), "=r"(r1), "=r"(r2), "=r"(r3) : "r"(adr));
}

__device__ __forceinline__ void cpa16(void* dst, const void* src) {
    uint32_t d = (uint32_t)__cvta_generic_to_shared(dst);
    asm volatile("cp.async.cg.shared.global [%0], [%1], 16;" :: "r"(d), "l"(src));
}
#define CP_COMMIT asm volatile("cp.async.commit_group;")

// ---------------- fused resize + k/v projection (fp16 out) ----------------------
__global__ __launch_bounds__(256)
void proj_kernel(const float* __restrict__ ctx,
                 const float* __restrict__ Wk, const float* __restrict__ bk,
                 const float* __restrict__ Wv, const float* __restrict__ bv) {
    __shared__ float sctx[NCC][64];
    __shared__ float sWk[NINTER*3], sbk[NINTER];
    __shared__ float sWv[NCQ*3], sbv[NCQ];
    int tid = threadIdx.x;
    int b = blockIdx.y, j0 = blockIdx.x * 64;

    for (int i = tid; i < NINTER*3; i += 256) sWk[i] = Wk[i];
    for (int i = tid; i < NCQ*3; i += 256)    sWv[i] = Wv[i];
    if (tid < NINTER) sbk[tid] = bk[tid];
    if (tid < NCQ)    sbv[tid] = bv[tid];

    if (tid < NCC * 64) {
        int c = tid >> 6, jj = tid & 63;
        int p = j0 + jj;
        int y = p >> 5, x = p & 31;
        float sy = 7.f * y + 3.f;
        float sx = 7.f * x + 3.f;
        int y0 = (int)floorf(sy), x0 = (int)floorf(sx);
        float fy = sy - y0, fx = sx - x0;
        int y1 = min(y0 + 1, NHC - 1), x1 = min(x0 + 1, NHC - 1);
        y0 = max(y0, 0); x0 = max(x0, 0);
        const float* base = ctx + ((size_t)b * NCC + c) * NHC * NHC;
        float v00 = base[y0 * NHC + x0], v01 = base[y0 * NHC + x1];
        float v10 = base[y1 * NHC + x0], v11 = base[y1 * NHC + x1];
        sctx[c][jj] = (1.f - fy) * ((1.f - fx) * v00 + fx * v01)
                    + fy * ((1.f - fx) * v10 + fx * v11);
    }
    __syncthreads();

    __half* kout = g_kT + ((size_t)b * NHW + j0) * NINTER;
#pragma unroll 4
    for (int o = tid; o < 64 * NINTER; o += 256) {
        int jj = o >> 7, c = o & 127;
        kout[(size_t)jj * NINTER + c] = __float2half_rn(
            sbk[c] + sWk[c*3]*sctx[0][jj] + sWk[c*3+1]*sctx[1][jj] + sWk[c*3+2]*sctx[2][jj]);
    }
    __half* vout = g_v + (size_t)b * NCQ * NHW + j0;
#pragma unroll 4
    for (int o = tid; o < NCQ * 64; o += 256) {
        int c = o >> 6, jj = o & 63;
        vout[(size_t)c * NHW + jj] = __float2half_rn(
            sbv[c] + sWv[c*3]*sctx[0][jj] + sWv[c*3+1]*sctx[1][jj] + sWv[c*3+2]*sctx[2][jj]);
    }
}

// ---------------- queryT transpose + half ----------------------------------------
__global__ void transpose_round(const float* __restrict__ in) {
    __shared__ float t[32][33];
    int b = blockIdx.z;
    int i0 = blockIdx.x * 32, c0 = blockIdx.y * 32;
    const float* ip = in + (size_t)b * NCQ * NHW;
    __half* op = g_queryT + (size_t)b * NHW * NCQ;
    t[threadIdx.y][threadIdx.x] = ip[(size_t)(c0 + threadIdx.y) * NHW + i0 + threadIdx.x];
    __syncthreads();
    op[(size_t)(i0 + threadIdx.y) * NCQ + c0 + threadIdx.x] =
        __float2half_rn(t[threadIdx.x][threadIdx.y]);
}

// ---------------- weight rounding + stats zero -------------------------------------
__global__ void prep_weights(const float* __restrict__ Wq, const float* __restrict__ Wp) {
    int i = blockIdx.x * blockDim.x + threadIdx.x;
    if (i < NINTER * NCQ) g_Wq[i] = __float2half_rn(Wq[i]);
    if (i < NCQ * NCQ)    g_Wp[i] = __float2half_rn(Wp[i]);
    if (i < NB * 2)       g_sums[i] = 0.f;
}

// ---------------- fp16 tensor-core ABT GEMM (ldmatrix) ------------------------------
#define HP 20   // smem row pitch in u32 (16 + 4 pad)
__global__ __launch_bounds__(256, 2)
void hgemm(const __half* __restrict__ A, const __half* __restrict__ B, void* __restrict__ Cv,
           size_t sA, size_t sB, size_t sC,
           const float* __restrict__ bias_m, const float* __restrict__ bias_n,
           int M, int N, int K, int outHalf, int doStats) {
    __shared__ uint32_t As[2][128 * HP];
    __shared__ uint32_t Bs[2][128 * HP];
    __shared__ float rs[8], rq[8];
    int b = blockIdx.z;
    A += (size_t)b * sA; B += (size_t)b * sB;
    int m0 = blockIdx.y * 128, n0 = blockIdx.x * 128;
    int tid = threadIdx.x, lane = tid & 31, wid = tid >> 5;
    int wm = wid >> 2, wn = wid & 3;
    int gid = lane >> 2, tig = lane & 3;
    int lrow8 = (lane & 7) | (((lane >> 3) & 1) << 3);
    int kblk4 = (lane >> 4) << 2;

    uint32_t As0 = (uint32_t)__cvta_generic_to_shared(&As[0][0]);
    uint32_t Bs0 = (uint32_t)__cvta_generic_to_shared(&Bs[0][0]);
    const uint32_t bufStep = 128 * HP * 4;

    float acc[4][4][4];
#pragma unroll
    for (int i = 0; i < 4; i++)
#pragma unroll
        for (int j = 0; j < 4; j++)
#pragma unroll
            for (int r = 0; r < 4; r++) acc[i][j][r] = 0.f;

    int seg0 = tid, seg1 = tid + 256;
    int lr0 = seg0 >> 2, ls0 = (seg0 & 3) * 8;
    int lr1 = seg1 >> 2, ls1 = (seg1 & 3) * 8;
    int nk = K / 32;
    uint4 ra0, ra1, rb0, rb1;

    ra0 = *(const uint4*)&A[(size_t)(m0 + lr0) * K + ls0];
    ra1 = *(const uint4*)&A[(size_t)(m0 + lr1) * K + ls1];
    rb0 = *(const uint4*)&B[(size_t)(n0 + lr0) * K + ls0];
    rb1 = *(const uint4*)&B[(size_t)(n0 + lr1) * K + ls1];
    {
        uint32_t* a = &As[0][lr0 * HP + (ls0 >> 1)];
        a[0] = ra0.x; a[1] = ra0.y; a[2] = ra0.z; a[3] = ra0.w;
        a = &As[0][lr1 * HP + (ls1 >> 1)];
        a[0] = ra1.x; a[1] = ra1.y; a[2] = ra1.z; a[3] = ra1.w;
        uint32_t* p = &Bs[0][lr0 * HP + (ls0 >> 1)];
        p[0] = rb0.x; p[1] = rb0.y; p[2] = rb0.z; p[3] = rb0.w;
        p = &Bs[0][lr1 * HP + (ls1 >> 1)];
        p[0] = rb1.x; p[1] = rb1.y; p[2] = rb1.z; p[3] = rb1.w;
    }
    __syncthreads();

    for (int kt = 0; kt < nk; kt++) {
        int cur = kt & 1;
        if (kt + 1 < nk) {
            int kb = (kt + 1) * 32;
            ra0 = *(const uint4*)&A[(size_t)(m0 + lr0) * K + kb + ls0];
            ra1 = *(const uint4*)&A[(size_t)(m0 + lr1) * K + kb + ls1];
            rb0 = *(const uint4*)&B[(size_t)(n0 + lr0) * K + kb + ls0];
            rb1 = *(const uint4*)&B[(size_t)(n0 + lr1) * K + kb + ls1];
        }
#pragma unroll
        for (int ks = 0; ks < 2; ks++) {
            int col = ks * 8 + kblk4;
            uint32_t afr[4][4], bfr[4][2];
#pragma unroll
            for (int mt = 0; mt < 4; mt++) {
                int row = wm * 64 + mt * 16 + lrow8;
                ldsm4(afr[mt][0], afr[mt][1], afr[mt][2], afr[mt][3],
                      As0 + cur * bufStep + (uint32_t)(row * HP + col) * 4);
            }
#pragma unroll
            for (int p = 0; p < 2; p++) {
                int row = wn * 32 + p * 16 + lrow8;
                ldsm4(bfr[2*p][0], bfr[2*p+1][0], bfr[2*p][1], bfr[2*p+1][1],
                      Bs0 + cur * bufStep + (uint32_t)(row * HP + col) * 4);
            }
#pragma unroll
            for (int mt = 0; mt < 4; mt++)
#pragma unroll
                for (int nt = 0; nt < 4; nt++)
                    mma_f16(acc[mt][nt], afr[mt][0], afr[mt][1], afr[mt][2], afr[mt][3],
                            bfr[nt][0], bfr[nt][1]);
        }
        if (kt + 1 < nk) {
            int nxt = cur ^ 1;
            uint32_t* a = &As[nxt][lr0 * HP + (ls0 >> 1)];
            a[0] = ra0.x; a[1] = ra0.y; a[2] = ra0.z; a[3] = ra0.w;
            a = &As[nxt][lr1 * HP + (ls1 >> 1)];
            a[0] = ra1.x; a[1] = ra1.y; a[2] = ra1.z; a[3] = ra1.w;
            uint32_t* p = &Bs[nxt][lr0 * HP + (ls0 >> 1)];
            p[0] = rb0.x; p[1] = rb0.y; p[2] = rb0.z; p[3] = rb0.w;
            p = &Bs[nxt][lr1 * HP + (ls1 >> 1)];
            p[0] = rb1.x; p[1] = rb1.y; p[2] = rb1.z; p[3] = rb1.w;
        }
        __syncthreads();
    }

    float ls = 0.f, lq = 0.f;
#pragma unroll
    for (int mt = 0; mt < 4; mt++) {
#pragma unroll
        for (int nt = 0; nt < 4; nt++) {
            int row0 = m0 + wm * 64 + mt * 16 + gid;
            int col  = n0 + wn * 32 + nt * 8 + tig * 2;
#pragma unroll
            for (int h = 0; h < 2; h++) {
                int row = row0 + h * 8;
                float x = acc[mt][nt][h * 2], y = acc[mt][nt][h * 2 + 1];
                if (bias_m) { float bm = bias_m[row]; x += bm; y += bm; }
                if (bias_n) { x += bias_n[col]; y += bias_n[col + 1]; }
                if (doStats) { ls += x + y; lq += x * x + y * y; }
                if (outHalf) {
                    uint32_t* C = (uint32_t*)Cv + ((size_t)b * sC + (size_t)row * N + col) / 2;
                    *C = pk2(x, y);
                } else {
                    float* C = (float*)Cv + (size_t)b * sC + (size_t)row * N + col;
                    float2 r; r.x = x; r.y = y;
                    *(float2*)C = r;
                }
            }
        }
    }
    if (doStats) {
#pragma unroll
        for (int o = 16; o; o >>= 1) {
            ls += __shfl_xor_sync(0xffffffffu, ls, o);
            lq += __shfl_xor_sync(0xffffffffu, lq, o);
        }
        if (lane == 0) { rs[wid] = ls; rq[wid] = lq; }
        __syncthreads();
        if (tid == 0) {
            float ts = 0.f, tq = 0.f;
#pragma unroll
            for (int i = 0; i < 8; i++) { ts += rs[i]; tq += rq[i]; }
            atomicAdd(&g_sums[b * 2], ts);
            atomicAdd(&g_sums[b * 2 + 1], tq);
        }
    }
}

// ---------------- flash attention fp16 v3: ldmatrix + double-buffered K,V ----------
// IT=128, JT=64, 512 threads, 3 syncs/iter, prefetch window = ~1 iteration.
// smem u32: Qs 128x64, Ks 2x64x64, Vs 2x256x32, Ps 128x32; floats redm 2x128, m_s 128,
// lred 2x128.
#define F_SMEM_BYTES ((128*64 + 2*64*64 + 2*256*32 + 128*32) * 4 + (128*2 + 128 + 128*2) * 4)

__global__ __launch_bounds__(512, 1)
void flash_kernel(const __half* __restrict__ qT, const __half* __restrict__ kT,
                  const __half* __restrict__ v, const __half* __restrict__ queryT,
                  __half* __restrict__ X) {
    extern __shared__ uint32_t smu[];
    uint32_t* Qs = smu;                    // 128 x 64
    uint32_t* Ks = Qs + 128 * 64;          // 2 x 64 x 64
    uint32_t* Vs = Ks + 2 * 64 * 64;       // 2 x 256 x 32
    uint32_t* Ps = Vs + 2 * 256 * 32;      // 128 x 32
    float* redm = (float*)(Ps + 128 * 32); // 128 x 2
    float* m_s  = redm + 128 * 2;          // 128
    float* lred = m_s + 128;               // 128 x 2

    uint32_t Qs_b = (uint32_t)__cvta_generic_to_shared(Qs);
    uint32_t Ks_b = (uint32_t)__cvta_generic_to_shared(Ks);
    uint32_t Vs_b = (uint32_t)__cvta_generic_to_shared(Vs);
    uint32_t Ps_b = (uint32_t)__cvta_generic_to_shared(Ps);

    int b = blockIdx.y, i0 = blockIdx.x * 128;
    const __half* qTb = qT + ((size_t)b * NHW + i0) * NINTER;
    const __half* kTb = kT + (size_t)b * NHW * NINTER;
    const __half* vb  = v  + (size_t)b * NCQ * NHW;

    int tid = threadIdx.x, lane = tid & 31, w = tid >> 5;
    int gid = lane >> 2, tig = lane & 3;
    int wm1 = w >> 1, wn1 = w & 1;         // gemm1: 8(m) x 2(n), warp tile 16x32
    int wm2 = w >> 2, wn2 = w & 3;         // gemm2: 4(m) x 4(n), warp tile 32x64
    int qm = gid << 2;
    int lrow8 = (lane & 7) | (((lane >> 3) & 1) << 3);
    int kblk4 = (lane >> 4) << 2;
    int swl = (lane & 7) << 2;

    // load Q tile 128x128 halves (swizzled u32x4 stores)
#pragma unroll
    for (int it = 0; it < 4; it++) {
        int id = tid + it * 512;
        int r = id >> 4, c4 = (id & 15) << 2;
        uint4 vq = *(const uint4*)&qTb[(size_t)r * NINTER + c4 * 2];
        *(uint4*)&Qs[r * 64 + (c4 ^ ((r & 7) << 2))] = vq;
    }
    if (tid < 128) m_s[tid] = -1e30f;

    // prologue: group0 = K0 + V0
#pragma unroll
    for (int it = 0; it < 2; it++) {
        int id = tid + it * 512;
        int r = id >> 4, c4 = (id & 15) << 2;
        cpa16(&Ks[r * 64 + (c4 ^ ((r & 7) << 2))], &kTb[(size_t)r * NINTER + c4 * 2]);
    }
#pragma unroll
    for (int it = 0; it < 4; it++) {
        int id = tid + it * 512;
        int r = id >> 3, c4 = (id & 7) << 2;
        cpa16(&Vs[r * 32 + (c4 ^ ((r & 7) << 2))], &vb[(size_t)r * NHW + c4 * 2]);
    }
    CP_COMMIT;

    float oa[2][8][4];
#pragma unroll
    for (int mt = 0; mt < 2; mt++)
#pragma unroll
        for (int nt = 0; nt < 8; nt++)
#pragma unroll
            for (int r = 0; r < 4; r++) oa[mt][nt][r] = 0.f;
    float lp0 = 0.f, lp1 = 0.f;
    int r0 = wm1 * 16 + gid, r1 = r0 + 8;

    // gemm1 lane bases
    uint32_t qadr  = Qs_b + (uint32_t)((wm1 * 16 + lrow8) * 64) * 4;
    uint32_t kadrA = Ks_b + (uint32_t)((wn1 * 32 + lrow8) * 64) * 4;
    uint32_t kadrB = kadrA + 16 * 64 * 4;
    // gemm2 lane bases
    uint32_t padrA = Ps_b + (uint32_t)((wm2 * 32 + lrow8) * 32) * 4;
    uint32_t padrB = padrA + 16 * 32 * 4;
    uint32_t vadr0 = Vs_b + (uint32_t)((wn2 * 64 + lrow8) * 32) * 4;

    for (int t = 0; t < 16; t++) {
        int buf = t & 1;
        uint32_t kOff = (uint32_t)buf * (64 * 64 * 4);
        uint32_t vOff = (uint32_t)buf * (256 * 32 * 4);

        asm volatile("cp.async.wait_group 0;");
        __syncthreads();        // (1) K(t),V(t) visible; all warps past gemm2(t-1)

        // ---- gemm1: S(16x32 per warp) = Q x K^T ----
        float sc[4][4];
#pragma unroll
        for (int nt = 0; nt < 4; nt++)
#pragma unroll
            for (int r = 0; r < 4; r++) sc[nt][r] = 0.f;
#pragma unroll
        for (int s = 0; s < 8; s++) {
            uint32_t cb = (uint32_t)(((s * 8 + kblk4) ^ swl) * 4);
            uint32_t a0, a1, a2, a3, b00, b01, b10, b11, b20, b21, b30, b31;
            ldsm4(a0, a1, a2, a3, qadr + cb);
            ldsm4(b00, b01, b10, b11, kadrA + kOff + cb);
            ldsm4(b20, b21, b30, b31, kadrB + kOff + cb);
            mma_f16(sc[0], a0, a1, a2, a3, b00, b10);
            mma_f16(sc[1], a0, a1, a2, a3, b01, b11);
            mma_f16(sc[2], a0, a1, a2, a3, b20, b30);
            mma_f16(sc[3], a0, a1, a2, a3, b21, b31);
        }

        // ---- tile row max ----
        float mx0 = -1e30f, mx1 = -1e30f;
#pragma unroll
        for (int nt = 0; nt < 4; nt++) {
            mx0 = fmaxf(mx0, fmaxf(sc[nt][0], sc[nt][1]));
            mx1 = fmaxf(mx1, fmaxf(sc[nt][2], sc[nt][3]));
        }
        mx0 = fmaxf(mx0, __shfl_xor_sync(0xffffffffu, mx0, 1));
        mx0 = fmaxf(mx0, __shfl_xor_sync(0xffffffffu, mx0, 2));
        mx1 = fmaxf(mx1, __shfl_xor_sync(0xffffffffu, mx1, 1));
        mx1 = fmaxf(mx1, __shfl_xor_sync(0xffffffffu, mx1, 2));
        if (tig == 0) { redm[r0 * 2 + wn1] = mx0; redm[r1 * 2 + wn1] = mx1; }
        __syncthreads();        // (2/A) redm visible; gemm1 done reading Ks[buf^1 is free]

        // prefetch K(t+1), V(t+1) into alternate buffers (readers all finished)
        if (t < 15) {
            int j0 = (t + 1) * 64;
            uint32_t* kd = &Ks[(buf ^ 1) * 64 * 64];
            uint32_t* vd = &Vs[(buf ^ 1) * 256 * 32];
#pragma unroll
            for (int it = 0; it < 2; it++) {
                int id = tid + it * 512;
                int r = id >> 4, c4 = (id & 15) << 2;
                cpa16(&kd[r * 64 + (c4 ^ ((r & 7) << 2))],
                      &kTb[(size_t)(j0 + r) * NINTER + c4 * 2]);
            }
#pragma unroll
            for (int it = 0; it < 4; it++) {
                int id = tid + it * 512;
                int r = id >> 3, c4 = (id & 7) << 2;
                cpa16(&vd[r * 32 + (c4 ^ ((r & 7) << 2))],
                      &vb[(size_t)r * NHW + j0 + c4 * 2]);
            }
            CP_COMMIT;
        }

        // ---- P = exp(s - mnew) fp16 -> Ps, l update, O rescale ----
        float m_old0 = m_s[r0], m_old1 = m_s[r1];
        float mn0 = fmaxf(m_old0, fmaxf(redm[r0 * 2], redm[r0 * 2 + 1]));
        float mn1 = fmaxf(m_old1, fmaxf(redm[r1 * 2], redm[r1 * 2 + 1]));
        float al0 = __expf(m_old0 - mn0), al1 = __expf(m_old1 - mn1);
        float s0 = 0.f, s1 = 0.f;
#pragma unroll
        for (int nt = 0; nt < 4; nt++) {
            float e0 = __expf(sc[nt][0] - mn0);
            float e1 = __expf(sc[nt][1] - mn0);
            float e2 = __expf(sc[nt][2] - mn1);
            float e3 = __expf(sc[nt][3] - mn1);
            s0 += e0 + e1; s1 += e2 + e3;
            int col = (wn1 * 16 + nt * 4 + tig) ^ qm;
            Ps[r0 * 32 + col] = pk2(e0, e1);
            Ps[r1 * 32 + col] = pk2(e2, e3);
        }
        lp0 = lp0 * al0 + s0;
        lp1 = lp1 * al1 + s1;

        float alo[2][2];
#pragma unroll
        for (int mt = 0; mt < 2; mt++) {
            int rr0 = wm2 * 32 + mt * 16 + gid, rr1 = rr0 + 8;
            float mo = m_s[rr0];
            alo[mt][0] = __expf(mo - fmaxf(mo, fmaxf(redm[rr0 * 2], redm[rr0 * 2 + 1])));
            mo = m_s[rr1];
            alo[mt][1] = __expf(mo - fmaxf(mo, fmaxf(redm[rr1 * 2], redm[rr1 * 2 + 1])));
        }
#pragma unroll
        for (int mt = 0; mt < 2; mt++)
#pragma unroll
            for (int nt = 0; nt < 8; nt++) {
                oa[mt][nt][0] *= alo[mt][0]; oa[mt][nt][1] *= alo[mt][0];
                oa[mt][nt][2] *= alo[mt][1]; oa[mt][nt][3] *= alo[mt][1];
            }
        __syncthreads();        // (3/B) Ps visible; m_s readers done

        if (wn1 == 0 && tig == 0) { m_s[r0] = mn0; m_s[r1] = mn1; }

        // ---- gemm2: O(32x64 per warp) += P x V ----
#pragma unroll
        for (int k = 0; k < 4; k++) {
            uint32_t cb = (uint32_t)(((k * 8 + kblk4) ^ swl) * 4);
            uint32_t p00, p01, p02, p03, p10, p11, p12, p13;
            ldsm4(p00, p01, p02, p03, padrA + cb);
            ldsm4(p10, p11, p12, p13, padrB + cb);
            uint32_t vb0[8], vb1[8];
#pragma unroll
            for (int p = 0; p < 4; p++) {
                ldsm4(vb0[2*p], vb0[2*p+1], vb1[2*p], vb1[2*p+1],
                      vadr0 + vOff + (uint32_t)(p * 16 * 32 * 4) + cb);
            }
#pragma unroll
            for (int nt = 0; nt < 8; nt++) {
                mma_f16(oa[0][nt], p00, p01, p02, p03, vb0[nt], vb1[nt]);
                mma_f16(oa[1][nt], p10, p11, p12, p13, vb0[nt], vb1[nt]);
            }
        }
    }

    // final l: quad reduce, combine halves via smem
    lp0 += __shfl_xor_sync(0xffffffffu, lp0, 1);
    lp0 += __shfl_xor_sync(0xffffffffu, lp0, 2);
    lp1 += __shfl_xor_sync(0xffffffffu, lp1, 1);
    lp1 += __shfl_xor_sync(0xffffffffu, lp1, 2);
    if (tig == 0) { lred[r0 * 2 + wn1] = lp0; lred[r1 * 2 + wn1] = lp1; }
    __syncthreads();

    // epilogue: O/l + residual -> half X'
    uint32_t* Xb = (uint32_t*)(X + ((size_t)b * NHW + i0) * NCQ);
    const uint32_t* qres = (const uint32_t*)(queryT + ((size_t)b * NHW + i0) * NCQ);
#pragma unroll
    for (int mt = 0; mt < 2; mt++) {
        int rr0 = wm2 * 32 + mt * 16 + gid, rr1 = rr0 + 8;
        float inv0 = 1.f / (lred[rr0 * 2] + lred[rr0 * 2 + 1]);
        float inv1 = 1.f / (lred[rr1 * 2] + lred[rr1 * 2 + 1]);
#pragma unroll
        for (int nt = 0; nt < 8; nt++) {
            int cu = wn2 * 32 + nt * 4 + tig;
            float2 q0 = up2(qres[rr0 * 128 + cu]);
            float2 q1 = up2(qres[rr1 * 128 + cu]);
            Xb[rr0 * 128 + cu] = pk2(oa[mt][nt][0] * inv0 + q0.x,
                                     oa[mt][nt][1] * inv0 + q0.y);
            Xb[rr1 * 128 + cu] = pk2(oa[mt][nt][2] * inv1 + q1.x,
                                     oa[mt][nt][3] * inv1 + q1.y);
        }
    }
}

// ---------------- normalize + affine -> out (float4) --------------------------------
__global__ void norm_kernel(const float* __restrict__ gamma, const float* __restrict__ beta,
                            float* __restrict__ out) {
    int idx = (blockIdx.x * blockDim.x + threadIdx.x) * 4;
    int b = idx >> 18;
    int o = (idx >> 10) & 255;
    float s = g_sums[b * 2], s2 = g_sums[b * 2 + 1];
    const float n = (float)GN_N;
    float mu = s / n;
    float var = s2 / n - mu * mu;
    float rstd = rsqrtf(var + 1e-5f);
    float ga = gamma[o] * rstd, be = beta[o] - mu * ga;
    float4 f = *(const float4*)&g_F[idx];
    float4 r;
    r.x = f.x * ga + be; r.y = f.y * ga + be;
    r.z = f.z * ga + be; r.w = f.w * ga + be;
    *(float4*)&out[idx] = r;
}

// ---------------- launch --------------------------------------------------------------
extern "C" void kernel_launch(void* const* d_in, const int* in_sizes, int n_in,
                              void* d_out, int out_size) {
    const float* query = (const float*)d_in[0];
    const float* ctx   = (const float*)d_in[1];
    const float* Wq = (const float*)d_in[2];  const float* bq = (const float*)d_in[3];
    const float* Wk = (const float*)d_in[4];  const float* bk = (const float*)d_in[5];
    const float* Wv = (const float*)d_in[6];  const float* bv = (const float*)d_in[7];
    const float* Wp = (const float*)d_in[8];  const float* bp = (const float*)d_in[9];
    const float* gamma = (const float*)d_in[10];
    const float* beta  = (const float*)d_in[11];
    float* out = (float*)d_out;

    __half *p_qT, *p_kT, *p_v, *p_X, *p_queryT, *p_Wq, *p_Wp;
    float *p_F;
    cudaGetSymbolAddress((void**)&p_qT, g_qT);
    cudaGetSymbolAddress((void**)&p_kT, g_kT);
    cudaGetSymbolAddress((void**)&p_v, g_v);
    cudaGetSymbolAddress((void**)&p_X, g_X);
    cudaGetSymbolAddress((void**)&p_F, g_F);
    cudaGetSymbolAddress((void**)&p_queryT, g_queryT);
    cudaGetSymbolAddress((void**)&p_Wq, g_Wq);
    cudaGetSymbolAddress((void**)&p_Wp, g_Wp);

    static int smem_set = 0;
    if (!smem_set) {
        cudaFuncSetAttribute(flash_kernel, cudaFuncAttributeMaxDynamicSharedMemorySize,
                             F_SMEM_BYTES);
        smem_set = 1;
    }

    // preprocessing
    prep_weights<<<256, 256>>>(Wq, Wp);
    proj_kernel<<<dim3(NHW / 64, NB), 256>>>(ctx, Wk, bk, Wv, bv);
    transpose_round<<<dim3(NHW / 32, NCQ / 32, NB), dim3(32, 32)>>>(query);

    // q projection: qT[i][c'] = queryT[i][:] . Wq[c'][:] + bq  -> half
    hgemm<<<dim3(NINTER / 128, NHW / 128, NB), 256>>>(
        p_queryT, p_Wq, p_qT,
        (size_t)NHW * NCQ, 0, (size_t)NHW * NINTER,
        nullptr, bq, NHW, NINTER, NCQ, 1, 0);

    // flash attention -> X'[b][i][c] half (with residual)
    flash_kernel<<<dim3(NHW / 128, NB), 512, F_SMEM_BYTES>>>(
        p_qT, p_kT, p_v, p_queryT, p_X);

    // fused conv: F[o][i] = Wp[o][:] . X'[i][:] + bp[o]  -> fp32 (+ GN stats)
    hgemm<<<dim3(NHW / 128, NCQ / 128, NB), 256>>>(
        p_Wp, p_X, p_F,
        0, (size_t)NHW * NCQ, (size_t)NCQ * NHW,
        bp, nullptr, NCQ, NHW, NCQ, 0, 1);

    // group norm apply
    norm_kernel<<<(NB * NCQ * NHW) / 1024, 256>>>(gamma, beta, out);
}